// round 6
// baseline (speedup 1.0000x reference)
#include <cuda_runtime.h>
#include <cuda_bf16.h>
#include <math.h>
#include <cstdint>

#define BB 8
#define LL 1024
#define DD 1024
#define HH 16
#define DK 64
#define ROWS_TOT (BB*LL)          // 8192

// Scratch (device globals)
__device__ __nv_bfloat16 g_qhH[(size_t)ROWS_TOT * DD];
__device__ __nv_bfloat16 g_qhL[(size_t)ROWS_TOT * DD];
__device__ __nv_bfloat16 g_khH[(size_t)ROWS_TOT * DD];
__device__ __nv_bfloat16 g_khL[(size_t)ROWS_TOT * DD];
__device__ float g_vh [(size_t)ROWS_TOT * DD];
__device__ float g_ctx[(size_t)ROWS_TOT * DD];
__device__ float g_proj[(size_t)ROWS_TOT * DD];
__device__ __nv_bfloat16 g_asH[(size_t)ROWS_TOT * DD];
__device__ __nv_bfloat16 g_asL[(size_t)ROWS_TOT * DD];
__device__ __nv_bfloat16 g_wsH[(size_t)DD * DD];
__device__ __nv_bfloat16 g_wsL[(size_t)DD * DD];

// ---------------------------------------------------------------------------
// helpers
// ---------------------------------------------------------------------------
__device__ __forceinline__ uint32_t smem_u32(const void* p) {
    uint32_t a;
    asm("{ .reg .u64 t; cvta.to.shared.u64 t, %1; cvt.u32.u64 %0, t; }" : "=r"(a) : "l"(p));
    return a;
}
__device__ __forceinline__ void cp16(uint32_t dst, const void* src) {
    asm volatile("cp.async.cg.shared.global [%0], [%1], 16;" :: "r"(dst), "l"(src));
}
#define CP_COMMIT asm volatile("cp.async.commit_group;" ::: "memory")
#define CP_WAIT1  asm volatile("cp.async.wait_group 1;" ::: "memory")
#define CP_WAIT0  asm volatile("cp.async.wait_group 0;" ::: "memory")

__device__ __forceinline__ void mma_bf16(float* c, const uint32_t* a, const uint32_t* b) {
    asm volatile(
        "mma.sync.aligned.m16n8k16.row.col.f32.bf16.bf16.f32 "
        "{%0,%1,%2,%3},{%4,%5,%6,%7},{%8,%9},{%0,%1,%2,%3};"
        : "+f"(c[0]), "+f"(c[1]), "+f"(c[2]), "+f"(c[3])
        : "r"(a[0]), "r"(a[1]), "r"(a[2]), "r"(a[3]), "r"(b[0]), "r"(b[1]));
}
__device__ __forceinline__ unsigned f2tf(float x) {
    unsigned r;
    asm("cvt.rna.tf32.f32 %0, %1;" : "=r"(r) : "f"(x));
    return r;
}
__device__ __forceinline__ void mma_tf32(float c[4], const unsigned a[4], const unsigned b[2]) {
    asm volatile(
        "mma.sync.aligned.m16n8k8.row.col.f32.tf32.tf32.f32 "
        "{%0,%1,%2,%3},{%4,%5,%6,%7},{%8,%9},{%0,%1,%2,%3};"
        : "+f"(c[0]), "+f"(c[1]), "+f"(c[2]), "+f"(c[3])
        : "r"(a[0]), "r"(a[1]), "r"(a[2]), "r"(a[3]), "r"(b[0]), "r"(b[1]));
}

// ---------------------------------------------------------------------------
// bf16 hi/lo split
// ---------------------------------------------------------------------------
__global__ __launch_bounds__(256) void split_bf16(
    const float* __restrict__ x, __nv_bfloat16* __restrict__ hi,
    __nv_bfloat16* __restrict__ lo, int n4)
{
    int i = blockIdx.x * blockDim.x + threadIdx.x;
    if (i >= n4) return;
    float4 v = ((const float4*)x)[i];
    __nv_bfloat16 h0 = __float2bfloat16(v.x);
    __nv_bfloat16 h1 = __float2bfloat16(v.y);
    __nv_bfloat16 h2 = __float2bfloat16(v.z);
    __nv_bfloat16 h3 = __float2bfloat16(v.w);
    __nv_bfloat16 l0 = __float2bfloat16(v.x - __bfloat162float(h0));
    __nv_bfloat16 l1 = __float2bfloat16(v.y - __bfloat162float(h1));
    __nv_bfloat16 l2 = __float2bfloat16(v.z - __bfloat162float(h2));
    __nv_bfloat16 l3 = __float2bfloat16(v.w - __bfloat162float(h3));
    ((__nv_bfloat162*)hi)[i * 2]     = __nv_bfloat162(h0, h1);
    ((__nv_bfloat162*)hi)[i * 2 + 1] = __nv_bfloat162(h2, h3);
    ((__nv_bfloat162*)lo)[i * 2]     = __nv_bfloat162(l0, l1);
    ((__nv_bfloat162*)lo)[i * 2 + 1] = __nv_bfloat162(l2, l3);
}

// ===========================================================================
// bf16-split projection GEMM (unchanged from R4)
// ===========================================================================
#define PL_E 5120
#define PL_B (PL_E*2)
#define BUF_B (4*PL_B)
#define GEMM_SMEM (2*BUF_B)

__global__ __launch_bounds__(512) void gemm_bf16(
    const __nv_bfloat16* __restrict__ Ah, const __nv_bfloat16* __restrict__ Al,
    const __nv_bfloat16* __restrict__ Bh, const __nv_bfloat16* __restrict__ Bl,
    const float* __restrict__ bias, const float* __restrict__ npm, float scale,
    float* __restrict__ outF, __nv_bfloat16* __restrict__ outH,
    __nv_bfloat16* __restrict__ outL)
{
    extern __shared__ char sm[];
    const uint32_t smb = smem_u32(sm);
    const int tid = threadIdx.x, wid = tid >> 5, lane = tid & 31;
    const int g = lane >> 2, tg = lane & 3;
    const int bm = blockIdx.y * 128, bn = blockIdx.x * 128;
    const int wm = (wid & 1) * 64, wn = (wid >> 1) * 16;

    const __nv_bfloat16* srcs[4] = { Ah + (size_t)bm * DD, Al + (size_t)bm * DD,
                                     Bh + (size_t)bn * DD, Bl + (size_t)bn * DD };
    const int frow = tid >> 2, fc = tid & 3;

    float acc[4][2][4];
#pragma unroll
    for (int mi = 0; mi < 4; mi++)
#pragma unroll
        for (int ni = 0; ni < 2; ni++)
#pragma unroll
            for (int r = 0; r < 4; r++) acc[mi][ni][r] = 0.f;

#pragma unroll
    for (int i = 0; i < 4; i++)
        cp16(smb + i * PL_B + frow * 80 + fc * 16,
             srcs[i] + (size_t)frow * DD + fc * 8);
    CP_COMMIT;

    for (int kt = 0; kt < 32; kt++) {
        if (kt < 31) {
#pragma unroll
            for (int i = 0; i < 4; i++)
                cp16(smb + ((kt + 1) & 1) * BUF_B + i * PL_B + frow * 80 + fc * 16,
                     srcs[i] + (size_t)frow * DD + (kt + 1) * 32 + fc * 8);
            CP_COMMIT;
            CP_WAIT1;
        } else {
            CP_WAIT0;
        }
        __syncthreads();

        const __nv_bfloat16* buf = (const __nv_bfloat16*)(sm + (kt & 1) * BUF_B);
#pragma unroll
        for (int ks = 0; ks < 2; ks++) {
            uint32_t a_h[4][4], a_l[4][4], b_h[2][2], b_l[2][2];
#pragma unroll
            for (int mi = 0; mi < 4; mi++) {
                const __nv_bfloat16* p = buf + (wm + mi * 16 + g) * 40 + ks * 16 + 2 * tg;
                a_h[mi][0] = *(const uint32_t*)(p);
                a_h[mi][1] = *(const uint32_t*)(p + 8 * 40);
                a_h[mi][2] = *(const uint32_t*)(p + 8);
                a_h[mi][3] = *(const uint32_t*)(p + 8 * 40 + 8);
                a_l[mi][0] = *(const uint32_t*)(p + PL_E);
                a_l[mi][1] = *(const uint32_t*)(p + PL_E + 8 * 40);
                a_l[mi][2] = *(const uint32_t*)(p + PL_E + 8);
                a_l[mi][3] = *(const uint32_t*)(p + PL_E + 8 * 40 + 8);
            }
#pragma unroll
            for (int ni = 0; ni < 2; ni++) {
                const __nv_bfloat16* p = buf + 2 * PL_E + (wn + ni * 8 + g) * 40 + ks * 16 + 2 * tg;
                b_h[ni][0] = *(const uint32_t*)(p);
                b_h[ni][1] = *(const uint32_t*)(p + 8);
                b_l[ni][0] = *(const uint32_t*)(p + PL_E);
                b_l[ni][1] = *(const uint32_t*)(p + PL_E + 8);
            }
#pragma unroll
            for (int mi = 0; mi < 4; mi++)
#pragma unroll
                for (int ni = 0; ni < 2; ni++) {
                    mma_bf16(acc[mi][ni], a_h[mi], b_h[ni]);
                    mma_bf16(acc[mi][ni], a_h[mi], b_l[ni]);
                    mma_bf16(acc[mi][ni], a_l[mi], b_h[ni]);
                }
        }
        __syncthreads();
    }

#pragma unroll
    for (int mi = 0; mi < 4; mi++) {
        int r0 = bm + wm + mi * 16 + g, r1 = r0 + 8;
        float nv0 = npm[r0] * scale, nv1 = npm[r1] * scale;
#pragma unroll
        for (int ni = 0; ni < 2; ni++) {
            int c0 = bn + wn + ni * 8 + 2 * tg;
            float b0 = bias[c0], b1 = bias[c0 + 1];
            float v00 = (acc[mi][ni][0] + b0) * nv0, v01 = (acc[mi][ni][1] + b1) * nv0;
            float v10 = (acc[mi][ni][2] + b0) * nv1, v11 = (acc[mi][ni][3] + b1) * nv1;
            if (outF) {
                *(float2*)&outF[(size_t)r0 * DD + c0] = make_float2(v00, v01);
                *(float2*)&outF[(size_t)r1 * DD + c0] = make_float2(v10, v11);
            } else {
                __nv_bfloat16 h00 = __float2bfloat16(v00), h01 = __float2bfloat16(v01);
                __nv_bfloat16 h10 = __float2bfloat16(v10), h11 = __float2bfloat16(v11);
                *(__nv_bfloat162*)&outH[(size_t)r0 * DD + c0] = __nv_bfloat162(h00, h01);
                *(__nv_bfloat162*)&outH[(size_t)r1 * DD + c0] = __nv_bfloat162(h10, h11);
                *(__nv_bfloat162*)&outL[(size_t)r0 * DD + c0] = __nv_bfloat162(
                    __float2bfloat16(v00 - __bfloat162float(h00)),
                    __float2bfloat16(v01 - __bfloat162float(h01)));
                *(__nv_bfloat162*)&outL[(size_t)r1 * DD + c0] = __nv_bfloat162(
                    __float2bfloat16(v10 - __bfloat162float(h10)),
                    __float2bfloat16(v11 - __bfloat162float(h11)));
            }
        }
    }
}

// ===========================================================================
// S-GEMM: scores = Qh·Kh^T (bf16-split 3-term) per (b,h), 128x128 tiles,
// K=64 single shot. 512 threads (16 warps: 4 row-groups x 4 col-groups).
// Writes raw scores into the attn region (softmax later, in-place).
// smem: 4 planes x [128][72] bf16 = 73728 B
// ===========================================================================
#define SG_PL 9216                     // plane elems 128*72
#define SG_SMEM (4 * SG_PL * 2)        // 73728 B

__global__ __launch_bounds__(512) void sgemm_s(
    const __nv_bfloat16* __restrict__ qhH, const __nv_bfloat16* __restrict__ qhL,
    const __nv_bfloat16* __restrict__ khH, const __nv_bfloat16* __restrict__ khL,
    float* __restrict__ attn)
{
    extern __shared__ char sm[];
    const uint32_t smb = smem_u32(sm);
    const __nv_bfloat16* Qh = (const __nv_bfloat16*)(sm);
    const __nv_bfloat16* Ql = Qh + SG_PL;
    const __nv_bfloat16* Kh = Qh + 2 * SG_PL;
    const __nv_bfloat16* Kl = Qh + 3 * SG_PL;

    const int tid = threadIdx.x, wid = tid >> 5, lane = tid & 31;
    const int g = lane >> 2, tg = lane & 3;
    const int bn = blockIdx.x * 128;      // k cols
    const int bm = blockIdx.y * 128;      // q rows
    const int bh = blockIdx.z;
    const int b = bh >> 4, h = bh & 15;
    const int wr = (wid & 3) * 32, wc = (wid >> 2) * 32;

    const __nv_bfloat16* src[4] = {
        qhH + ((size_t)b * LL + bm) * DD + h * DK,
        qhL + ((size_t)b * LL + bm) * DD + h * DK,
        khH + ((size_t)b * LL + bn) * DD + h * DK,
        khL + ((size_t)b * LL + bn) * DD + h * DK };

#pragma unroll
    for (int p = 0; p < 4; p++)
#pragma unroll
        for (int j = 0; j < 2; j++) {
            int idx = tid + 512 * j;          // 0..1023
            int row = idx >> 3, c8 = idx & 7;
            cp16(smb + p * SG_PL * 2 + row * 144 + c8 * 16,
                 src[p] + (size_t)row * DD + c8 * 8);
        }
    CP_COMMIT; CP_WAIT0;
    __syncthreads();

    float sacc[2][4][4];
#pragma unroll
    for (int mi = 0; mi < 2; mi++)
#pragma unroll
        for (int ni = 0; ni < 4; ni++)
#pragma unroll
            for (int r = 0; r < 4; r++) sacc[mi][ni][r] = 0.f;

#pragma unroll
    for (int ks = 0; ks < 4; ks++) {
        uint32_t a_h[2][4], a_l[2][4], b_h[4][2], b_l[4][2];
#pragma unroll
        for (int mi = 0; mi < 2; mi++) {
            const __nv_bfloat16* p = Qh + (wr + mi * 16 + g) * 72 + ks * 16 + 2 * tg;
            a_h[mi][0] = *(const uint32_t*)(p);
            a_h[mi][1] = *(const uint32_t*)(p + 8 * 72);
            a_h[mi][2] = *(const uint32_t*)(p + 8);
            a_h[mi][3] = *(const uint32_t*)(p + 8 * 72 + 8);
            a_l[mi][0] = *(const uint32_t*)(p + SG_PL);
            a_l[mi][1] = *(const uint32_t*)(p + SG_PL + 8 * 72);
            a_l[mi][2] = *(const uint32_t*)(p + SG_PL + 8);
            a_l[mi][3] = *(const uint32_t*)(p + SG_PL + 8 * 72 + 8);
        }
#pragma unroll
        for (int ni = 0; ni < 4; ni++) {
            const __nv_bfloat16* p = Kh + (wc + ni * 8 + g) * 72 + ks * 16 + 2 * tg;
            b_h[ni][0] = *(const uint32_t*)(p);
            b_h[ni][1] = *(const uint32_t*)(p + 8);
            b_l[ni][0] = *(const uint32_t*)(p + SG_PL);
            b_l[ni][1] = *(const uint32_t*)(p + SG_PL + 8);
        }
#pragma unroll
        for (int mi = 0; mi < 2; mi++)
#pragma unroll
            for (int ni = 0; ni < 4; ni++) {
                mma_bf16(sacc[mi][ni], a_h[mi], b_h[ni]);
                mma_bf16(sacc[mi][ni], a_h[mi], b_l[ni]);
                mma_bf16(sacc[mi][ni], a_l[mi], b_h[ni]);
            }
    }

#pragma unroll
    for (int mi = 0; mi < 2; mi++) {
        size_t r0 = (size_t)bh * LL + bm + wr + mi * 16 + g;
#pragma unroll
        for (int ni = 0; ni < 4; ni++) {
            int c = bn + wc + ni * 8 + 2 * tg;
            *(float2*)&attn[r0 * LL + c]        = make_float2(sacc[mi][ni][0], sacc[mi][ni][1]);
            *(float2*)&attn[(r0 + 8) * LL + c]  = make_float2(sacc[mi][ni][2], sacc[mi][ni][3]);
        }
    }
}

// ===========================================================================
// Fused masked-softmax (in-place on attn) + PV (tf32 mma)
// block = (b,h) x 32 q-rows, 256 threads (8 warps: 2 q-groups x 4 d-groups)
// smem: S [32][1028] f32 (131584 B) | V double buf 2 x [128][68] f32 (69632 B)
// ===========================================================================
#define SP_SSTR 1028
#define SP_VOFF 131584
#define SP_VBUF 34816                  // 128*68*4
#define SP_SMEM (SP_VOFF + 2*SP_VBUF)  // 201216 B

__global__ __launch_bounds__(256) void smpv_kernel(
    const float* __restrict__ vh, const int* __restrict__ mask,
    float* __restrict__ attn, float* __restrict__ ctx)
{
    extern __shared__ char sm[];
    const uint32_t smb = smem_u32(sm);
    float* S = (float*)sm;

    const int tid = threadIdx.x, wid = tid >> 5, lane = tid & 31;
    const int g = lane >> 2, tg = lane & 3;
    const int bh = blockIdx.x;
    const int b = bh >> 4, h = bh & 15;
    const int q0 = blockIdx.y * 32;

    float* attnBase = attn + ((size_t)bh * LL + q0) * LL;
    const float* vhp = vh + (size_t)b * LL * DD + h * DK;

    // ---- load S rows (32 x 1024 fp32) via cp.async ----
#pragma unroll
    for (int j = 0; j < 32; j++) {
        int idx = tid + 256 * j;               // 0..8191
        int row = idx >> 8, c4 = idx & 255;
        cp16(smb + row * (SP_SSTR * 4) + c4 * 16,
             attnBase + (size_t)row * LL + c4 * 4);
    }
    CP_COMMIT;
    // prefetch V chunk 0
#pragma unroll
    for (int j = 0; j < 8; j++) {
        int idx = tid + 256 * j;               // 0..2047
        int row = idx >> 4, c4 = idx & 15;
        cp16(smb + SP_VOFF + row * 272 + c4 * 16,
             vhp + (size_t)row * DD + c4 * 4);
    }
    CP_COMMIT;
    CP_WAIT1;                                   // S resident
    __syncthreads();

    // ---- mask + softmax, 8 warps x 4 rows, write attn in place ----
#pragma unroll
    for (int rr = 0; rr < 4; rr++) {
        int r = wid * 4 + rr;
        float* Sr = S + r * SP_SSTR;
        const int* mr = mask + ((size_t)b * LL + q0 + r) * LL;
        float m = -1e30f;
        for (int c = lane; c < 1024; c += 32) {
            float s = Sr[c];
            if (mr[c]) s = -1e30f;
            Sr[c] = s;
            m = fmaxf(m, s);
        }
#pragma unroll
        for (int o = 16; o; o >>= 1) m = fmaxf(m, __shfl_xor_sync(0xffffffffu, m, o));
        float sum = 0.f;
        for (int c = lane; c < 1024; c += 32) {
            float s = Sr[c];
            float e = (s <= -9e29f) ? 0.f : __expf(s - m);
            Sr[c] = e;
            sum += e;
        }
#pragma unroll
        for (int o = 16; o; o >>= 1) sum += __shfl_xor_sync(0xffffffffu, sum, o);
        float inv = 1.f / sum;
        float* dst = attnBase + (size_t)r * LL;
        for (int c = lane; c < 1024; c += 32) {
            float p = Sr[c] * inv;
            Sr[c] = p;
            dst[c] = p;
        }
    }
    __syncthreads();

    // ---- PV: warp tile 16q x 16d, V double-buffered chunks of 128 ----
    const int wq = wid & 1, wd = wid >> 1;
    float pacc[2][4];
#pragma unroll
    for (int ni = 0; ni < 2; ni++)
#pragma unroll
        for (int r = 0; r < 4; r++) pacc[ni][r] = 0.f;

    for (int vc = 0; vc < 8; vc++) {
        if (vc < 7) {
#pragma unroll
            for (int j = 0; j < 8; j++) {
                int idx = tid + 256 * j;
                int row = idx >> 4, c4 = idx & 15;
                cp16(smb + SP_VOFF + ((vc + 1) & 1) * SP_VBUF + row * 272 + c4 * 16,
                     vhp + (size_t)((vc + 1) * 128 + row) * DD + c4 * 4);
            }
            CP_COMMIT;
            CP_WAIT1;
        } else {
            CP_WAIT0;
        }
        __syncthreads();

        const float* Vs = (const float*)(sm + SP_VOFF + (vc & 1) * SP_VBUF);
#pragma unroll
        for (int kk = 0; kk < 16; kk++) {
            unsigned af[4], bf2[2];
            int c = vc * 128 + kk * 8 + tg;
            af[0] = f2tf(S[(wq * 16 + g) * SP_SSTR + c]);
            af[1] = f2tf(S[(wq * 16 + g + 8) * SP_SSTR + c]);
            af[2] = f2tf(S[(wq * 16 + g) * SP_SSTR + c + 4]);
            af[3] = f2tf(S[(wq * 16 + g + 8) * SP_SSTR + c + 4]);
#pragma unroll
            for (int ni = 0; ni < 2; ni++) {
                int vcol = wd * 16 + ni * 8 + g;
                bf2[0] = __float_as_uint(Vs[(kk * 8 + tg) * 68 + vcol]);
                bf2[1] = __float_as_uint(Vs[(kk * 8 + tg + 4) * 68 + vcol]);
                mma_tf32(pacc[ni], af, bf2);
            }
        }
        __syncthreads();
    }

#pragma unroll
    for (int ni = 0; ni < 2; ni++) {
        int c = h * DK + wd * 16 + ni * 8 + 2 * tg;
        size_t r0 = (size_t)b * LL + q0 + wq * 16 + g;
        *(float2*)&ctx[r0 * DD + c]       = make_float2(pacc[ni][0], pacc[ni][1]);
        *(float2*)&ctx[(r0 + 8) * DD + c] = make_float2(pacc[ni][2], pacc[ni][3]);
    }
}

// ---------------------------------------------------------------------------
// LayerNorm(proj + residual) * g + b
// ---------------------------------------------------------------------------
__global__ __launch_bounds__(256) void ln_kernel(
    const float* __restrict__ proj, const float* __restrict__ resid,
    const float* __restrict__ gam, const float* __restrict__ bet,
    float* __restrict__ out)
{
    __shared__ float red[8];
    const int row = blockIdx.x;
    const int tid = threadIdx.x;
    const int c0 = tid * 4;
    const int lane = tid & 31, wid = tid >> 5;

    float4 pv = *(const float4*)(proj + (size_t)row * DD + c0);
    float4 rv = *(const float4*)(resid + (size_t)row * DD + c0);
    float x0 = pv.x + rv.x, x1 = pv.y + rv.y, x2 = pv.z + rv.z, x3 = pv.w + rv.w;

    float s = x0 + x1 + x2 + x3;
#pragma unroll
    for (int o = 16; o; o >>= 1) s += __shfl_xor_sync(0xffffffffu, s, o);
    if (lane == 0) red[wid] = s;
    __syncthreads();
    float tot = (lane < 8) ? red[lane] : 0.f;
#pragma unroll
    for (int o = 4; o; o >>= 1) tot += __shfl_xor_sync(0xffffffffu, tot, o);
    tot = __shfl_sync(0xffffffffu, tot, 0);
    float mean = tot * (1.f / 1024.f);

    float d0 = x0 - mean, d1 = x1 - mean, d2 = x2 - mean, d3 = x3 - mean;
    float sq = d0 * d0 + d1 * d1 + d2 * d2 + d3 * d3;
#pragma unroll
    for (int o = 16; o; o >>= 1) sq += __shfl_xor_sync(0xffffffffu, sq, o);
    __syncthreads();
    if (lane == 0) red[wid] = sq;
    __syncthreads();
    float tot2 = (lane < 8) ? red[lane] : 0.f;
#pragma unroll
    for (int o = 4; o; o >>= 1) tot2 += __shfl_xor_sync(0xffffffffu, tot2, o);
    tot2 = __shfl_sync(0xffffffffu, tot2, 0);
    float k = rsqrtf(tot2 * (1.f / 1024.f) + 1e-5f);

    float4 gv = *(const float4*)(gam + c0);
    float4 bv = *(const float4*)(bet + c0);
    float4 ov;
    ov.x = d0 * k * gv.x + bv.x;
    ov.y = d1 * k * gv.y + bv.y;
    ov.z = d2 * k * gv.z + bv.z;
    ov.w = d3 * k * gv.w + bv.w;
    *(float4*)&out[(size_t)row * DD + c0] = ov;
}

// ---------------------------------------------------------------------------
extern "C" void kernel_launch(void* const* d_in, const int* in_sizes, int n_in,
                              void* d_out, int out_size)
{
    const float* q    = (const float*)d_in[0];
    const float* k    = (const float*)d_in[1];
    const float* v    = (const float*)d_in[2];
    const int*   mask = (const int*)  d_in[3];
    const float* npm  = (const float*)d_in[4];
    const float* Wq   = (const float*)d_in[5];
    const float* bq   = (const float*)d_in[6];
    const float* Wk   = (const float*)d_in[7];
    const float* bk   = (const float*)d_in[8];
    const float* Wv   = (const float*)d_in[9];
    const float* bv   = (const float*)d_in[10];
    const float* Wf   = (const float*)d_in[11];
    const float* bf   = (const float*)d_in[12];
    const float* ln_g = (const float*)d_in[13];
    const float* ln_b = (const float*)d_in[14];

    float* out  = (float*)d_out;                       // (B,L,D)
    float* attn = out + (size_t)BB * LL * DD;          // (B,H,L,L)

    __nv_bfloat16 *qhH, *qhL, *khH, *khL, *asH, *asL, *wsH, *wsL;
    float *vh, *ctx, *proj;
    cudaGetSymbolAddress((void**)&qhH, g_qhH);
    cudaGetSymbolAddress((void**)&qhL, g_qhL);
    cudaGetSymbolAddress((void**)&khH, g_khH);
    cudaGetSymbolAddress((void**)&khL, g_khL);
    cudaGetSymbolAddress((void**)&vh,  g_vh);
    cudaGetSymbolAddress((void**)&ctx, g_ctx);
    cudaGetSymbolAddress((void**)&proj, g_proj);
    cudaGetSymbolAddress((void**)&asH, g_asH);
    cudaGetSymbolAddress((void**)&asL, g_asL);
    cudaGetSymbolAddress((void**)&wsH, g_wsH);
    cudaGetSymbolAddress((void**)&wsL, g_wsL);

    cudaFuncSetAttribute(gemm_bf16, cudaFuncAttributeMaxDynamicSharedMemorySize, GEMM_SMEM);
    cudaFuncSetAttribute(sgemm_s, cudaFuncAttributeMaxDynamicSharedMemorySize, SG_SMEM);
    cudaFuncSetAttribute(smpv_kernel, cudaFuncAttributeMaxDynamicSharedMemorySize, SP_SMEM);

    const int nA4 = ROWS_TOT * DD / 4;
    const int nW4 = DD * DD / 4;
    dim3 gG(DD / 128, ROWS_TOT / 128);   // (8, 64)

    // Q projection -> bf16 planes (scale 1/8 folded)
    split_bf16<<<(nA4 + 255) / 256, 256>>>(q, asH, asL, nA4);
    split_bf16<<<(nW4 + 255) / 256, 256>>>(Wq, wsH, wsL, nW4);
    gemm_bf16<<<gG, 512, GEMM_SMEM>>>(asH, asL, wsH, wsL, bq, npm, 0.125f,
                                      nullptr, qhH, qhL);
    // K projection -> bf16 planes
    split_bf16<<<(nA4 + 255) / 256, 256>>>(k, asH, asL, nA4);
    split_bf16<<<(nW4 + 255) / 256, 256>>>(Wk, wsH, wsL, nW4);
    gemm_bf16<<<gG, 512, GEMM_SMEM>>>(asH, asL, wsH, wsL, bk, npm, 1.0f,
                                      nullptr, khH, khL);
    // V projection -> fp32
    split_bf16<<<(nA4 + 255) / 256, 256>>>(v, asH, asL, nA4);
    split_bf16<<<(nW4 + 255) / 256, 256>>>(Wv, wsH, wsL, nW4);
    gemm_bf16<<<gG, 512, GEMM_SMEM>>>(asH, asL, wsH, wsL, bv, npm, 1.0f,
                                      vh, nullptr, nullptr);

    // S = Q K^T into attn region, then fused masked-softmax + PV
    sgemm_s<<<dim3(8, 8, BB * HH), 512, SG_SMEM>>>(qhH, qhL, khH, khL, attn);
    smpv_kernel<<<dim3(BB * HH, LL / 32), 256, SP_SMEM>>>(vh, mask, attn, ctx);

    // Output projection -> fp32, then LN
    split_bf16<<<(nA4 + 255) / 256, 256>>>(ctx, asH, asL, nA4);
    split_bf16<<<(nW4 + 255) / 256, 256>>>(Wf, wsH, wsL, nW4);
    gemm_bf16<<<gG, 512, GEMM_SMEM>>>(asH, asL, wsH, wsL, bf, npm, 1.0f,
                                      proj, nullptr, nullptr);

    ln_kernel<<<ROWS_TOT, 256>>>(proj, q, ln_g, ln_b, out);
}

// round 7
// speedup vs baseline: 1.1255x; 1.1255x over previous
#include <cuda_runtime.h>
#include <cuda_bf16.h>
#include <math.h>
#include <cstdint>

#define BB 8
#define LL 1024
#define DD 1024
#define HH 16
#define DK 64
#define ROWS_TOT (BB*LL)          // 8192

// Scratch (device globals)
__device__ __nv_bfloat16 g_qhH[(size_t)ROWS_TOT * DD];
__device__ __nv_bfloat16 g_qhL[(size_t)ROWS_TOT * DD];
__device__ __nv_bfloat16 g_khH[(size_t)ROWS_TOT * DD];
__device__ __nv_bfloat16 g_khL[(size_t)ROWS_TOT * DD];
__device__ float g_vh [(size_t)ROWS_TOT * DD];
__device__ float g_ctx[(size_t)ROWS_TOT * DD];
__device__ float g_proj[(size_t)ROWS_TOT * DD];
__device__ __nv_bfloat16 g_asH[(size_t)ROWS_TOT * DD];
__device__ __nv_bfloat16 g_asL[(size_t)ROWS_TOT * DD];
__device__ __nv_bfloat16 g_wsH[(size_t)DD * DD];
__device__ __nv_bfloat16 g_wsL[(size_t)DD * DD];

// ---------------------------------------------------------------------------
// helpers
// ---------------------------------------------------------------------------
__device__ __forceinline__ uint32_t smem_u32(const void* p) {
    uint32_t a;
    asm("{ .reg .u64 t; cvta.to.shared.u64 t, %1; cvt.u32.u64 %0, t; }" : "=r"(a) : "l"(p));
    return a;
}
__device__ __forceinline__ void cp16(uint32_t dst, const void* src) {
    asm volatile("cp.async.cg.shared.global [%0], [%1], 16;" :: "r"(dst), "l"(src));
}
#define CP_COMMIT asm volatile("cp.async.commit_group;" ::: "memory")
#define CP_WAIT1  asm volatile("cp.async.wait_group 1;" ::: "memory")
#define CP_WAIT0  asm volatile("cp.async.wait_group 0;" ::: "memory")

__device__ __forceinline__ void mma_bf16(float* c, const uint32_t* a, const uint32_t* b) {
    asm volatile(
        "mma.sync.aligned.m16n8k16.row.col.f32.bf16.bf16.f32 "
        "{%0,%1,%2,%3},{%4,%5,%6,%7},{%8,%9},{%0,%1,%2,%3};"
        : "+f"(c[0]), "+f"(c[1]), "+f"(c[2]), "+f"(c[3])
        : "r"(a[0]), "r"(a[1]), "r"(a[2]), "r"(a[3]), "r"(b[0]), "r"(b[1]));
}
__device__ __forceinline__ unsigned f2tf(float x) {
    unsigned r;
    asm("cvt.rna.tf32.f32 %0, %1;" : "=r"(r) : "f"(x));
    return r;
}
__device__ __forceinline__ void mma_tf32(float c[4], const unsigned a[4], const unsigned b[2]) {
    asm volatile(
        "mma.sync.aligned.m16n8k8.row.col.f32.tf32.tf32.f32 "
        "{%0,%1,%2,%3},{%4,%5,%6,%7},{%8,%9},{%0,%1,%2,%3};"
        : "+f"(c[0]), "+f"(c[1]), "+f"(c[2]), "+f"(c[3])
        : "r"(a[0]), "r"(a[1]), "r"(a[2]), "r"(a[3]), "r"(b[0]), "r"(b[1]));
}

// ---------------------------------------------------------------------------
// bf16 hi/lo split
// ---------------------------------------------------------------------------
__global__ __launch_bounds__(256) void split_bf16(
    const float* __restrict__ x, __nv_bfloat16* __restrict__ hi,
    __nv_bfloat16* __restrict__ lo, int n4)
{
    int i = blockIdx.x * blockDim.x + threadIdx.x;
    if (i >= n4) return;
    float4 v = ((const float4*)x)[i];
    __nv_bfloat16 h0 = __float2bfloat16(v.x);
    __nv_bfloat16 h1 = __float2bfloat16(v.y);
    __nv_bfloat16 h2 = __float2bfloat16(v.z);
    __nv_bfloat16 h3 = __float2bfloat16(v.w);
    __nv_bfloat16 l0 = __float2bfloat16(v.x - __bfloat162float(h0));
    __nv_bfloat16 l1 = __float2bfloat16(v.y - __bfloat162float(h1));
    __nv_bfloat16 l2 = __float2bfloat16(v.z - __bfloat162float(h2));
    __nv_bfloat16 l3 = __float2bfloat16(v.w - __bfloat162float(h3));
    ((__nv_bfloat162*)hi)[i * 2]     = __nv_bfloat162(h0, h1);
    ((__nv_bfloat162*)hi)[i * 2 + 1] = __nv_bfloat162(h2, h3);
    ((__nv_bfloat162*)lo)[i * 2]     = __nv_bfloat162(l0, l1);
    ((__nv_bfloat162*)lo)[i * 2 + 1] = __nv_bfloat162(l2, l3);
}

// ===========================================================================
// bf16-split projection GEMM (R4, proven)
// ===========================================================================
#define PL_E 5120
#define PL_B (PL_E*2)
#define BUF_B (4*PL_B)
#define GEMM_SMEM (2*BUF_B)

__global__ __launch_bounds__(512) void gemm_bf16(
    const __nv_bfloat16* __restrict__ Ah, const __nv_bfloat16* __restrict__ Al,
    const __nv_bfloat16* __restrict__ Bh, const __nv_bfloat16* __restrict__ Bl,
    const float* __restrict__ bias, const float* __restrict__ npm, float scale,
    float* __restrict__ outF, __nv_bfloat16* __restrict__ outH,
    __nv_bfloat16* __restrict__ outL)
{
    extern __shared__ char sm[];
    const uint32_t smb = smem_u32(sm);
    const int tid = threadIdx.x, wid = tid >> 5, lane = tid & 31;
    const int g = lane >> 2, tg = lane & 3;
    const int bm = blockIdx.y * 128, bn = blockIdx.x * 128;
    const int wm = (wid & 1) * 64, wn = (wid >> 1) * 16;

    const __nv_bfloat16* srcs[4] = { Ah + (size_t)bm * DD, Al + (size_t)bm * DD,
                                     Bh + (size_t)bn * DD, Bl + (size_t)bn * DD };
    const int frow = tid >> 2, fc = tid & 3;

    float acc[4][2][4];
#pragma unroll
    for (int mi = 0; mi < 4; mi++)
#pragma unroll
        for (int ni = 0; ni < 2; ni++)
#pragma unroll
            for (int r = 0; r < 4; r++) acc[mi][ni][r] = 0.f;

#pragma unroll
    for (int i = 0; i < 4; i++)
        cp16(smb + i * PL_B + frow * 80 + fc * 16,
             srcs[i] + (size_t)frow * DD + fc * 8);
    CP_COMMIT;

    for (int kt = 0; kt < 32; kt++) {
        if (kt < 31) {
#pragma unroll
            for (int i = 0; i < 4; i++)
                cp16(smb + ((kt + 1) & 1) * BUF_B + i * PL_B + frow * 80 + fc * 16,
                     srcs[i] + (size_t)frow * DD + (kt + 1) * 32 + fc * 8);
            CP_COMMIT;
            CP_WAIT1;
        } else {
            CP_WAIT0;
        }
        __syncthreads();

        const __nv_bfloat16* buf = (const __nv_bfloat16*)(sm + (kt & 1) * BUF_B);
#pragma unroll
        for (int ks = 0; ks < 2; ks++) {
            uint32_t a_h[4][4], a_l[4][4], b_h[2][2], b_l[2][2];
#pragma unroll
            for (int mi = 0; mi < 4; mi++) {
                const __nv_bfloat16* p = buf + (wm + mi * 16 + g) * 40 + ks * 16 + 2 * tg;
                a_h[mi][0] = *(const uint32_t*)(p);
                a_h[mi][1] = *(const uint32_t*)(p + 8 * 40);
                a_h[mi][2] = *(const uint32_t*)(p + 8);
                a_h[mi][3] = *(const uint32_t*)(p + 8 * 40 + 8);
                a_l[mi][0] = *(const uint32_t*)(p + PL_E);
                a_l[mi][1] = *(const uint32_t*)(p + PL_E + 8 * 40);
                a_l[mi][2] = *(const uint32_t*)(p + PL_E + 8);
                a_l[mi][3] = *(const uint32_t*)(p + PL_E + 8 * 40 + 8);
            }
#pragma unroll
            for (int ni = 0; ni < 2; ni++) {
                const __nv_bfloat16* p = buf + 2 * PL_E + (wn + ni * 8 + g) * 40 + ks * 16 + 2 * tg;
                b_h[ni][0] = *(const uint32_t*)(p);
                b_h[ni][1] = *(const uint32_t*)(p + 8);
                b_l[ni][0] = *(const uint32_t*)(p + PL_E);
                b_l[ni][1] = *(const uint32_t*)(p + PL_E + 8);
            }
#pragma unroll
            for (int mi = 0; mi < 4; mi++)
#pragma unroll
                for (int ni = 0; ni < 2; ni++) {
                    mma_bf16(acc[mi][ni], a_h[mi], b_h[ni]);
                    mma_bf16(acc[mi][ni], a_h[mi], b_l[ni]);
                    mma_bf16(acc[mi][ni], a_l[mi], b_h[ni]);
                }
        }
        __syncthreads();
    }

#pragma unroll
    for (int mi = 0; mi < 4; mi++) {
        int r0 = bm + wm + mi * 16 + g, r1 = r0 + 8;
        float nv0 = npm[r0] * scale, nv1 = npm[r1] * scale;
#pragma unroll
        for (int ni = 0; ni < 2; ni++) {
            int c0 = bn + wn + ni * 8 + 2 * tg;
            float b0 = bias[c0], b1 = bias[c0 + 1];
            float v00 = (acc[mi][ni][0] + b0) * nv0, v01 = (acc[mi][ni][1] + b1) * nv0;
            float v10 = (acc[mi][ni][2] + b0) * nv1, v11 = (acc[mi][ni][3] + b1) * nv1;
            if (outF) {
                *(float2*)&outF[(size_t)r0 * DD + c0] = make_float2(v00, v01);
                *(float2*)&outF[(size_t)r1 * DD + c0] = make_float2(v10, v11);
            } else {
                __nv_bfloat16 h00 = __float2bfloat16(v00), h01 = __float2bfloat16(v01);
                __nv_bfloat16 h10 = __float2bfloat16(v10), h11 = __float2bfloat16(v11);
                *(__nv_bfloat162*)&outH[(size_t)r0 * DD + c0] = __nv_bfloat162(h00, h01);
                *(__nv_bfloat162*)&outH[(size_t)r1 * DD + c0] = __nv_bfloat162(h10, h11);
                *(__nv_bfloat162*)&outL[(size_t)r0 * DD + c0] = __nv_bfloat162(
                    __float2bfloat16(v00 - __bfloat162float(h00)),
                    __float2bfloat16(v01 - __bfloat162float(h01)));
                *(__nv_bfloat162*)&outL[(size_t)r1 * DD + c0] = __nv_bfloat162(
                    __float2bfloat16(v10 - __bfloat162float(h10)),
                    __float2bfloat16(v11 - __bfloat162float(h11)));
            }
        }
    }
}

// ===========================================================================
// Fused attention: block = (b,h) x 32 q-rows, 512 threads (16 warps)
// S = QK^T (bf16-split, K double-buffered) -> mask+softmax -> PV (tf32, V dbuf)
// S stays in smem; attn written exactly once.
// smem: S[32][1028] f32 131584 | Qh/Ql 2x4608 | K dbuf 2x36864 = 214528 B
// ===========================================================================
#define SSTR 1028
#define QOFF 131584
#define KOFF (QOFF + 9216)
#define KBUF 36864
#define KPLE 9216                       // plane elems (18432 B / 2)
#define ATT_SMEM (KOFF + 2*KBUF)        // 214528

__global__ __launch_bounds__(512) void attn_kernel(
    const __nv_bfloat16* __restrict__ qhH, const __nv_bfloat16* __restrict__ qhL,
    const __nv_bfloat16* __restrict__ khH, const __nv_bfloat16* __restrict__ khL,
    const float* __restrict__ vh, const int* __restrict__ mask,
    float* __restrict__ attn, float* __restrict__ ctx)
{
    extern __shared__ char sm[];
    const uint32_t smb = smem_u32(sm);
    float* S = (float*)sm;
    const __nv_bfloat16* Qh = (const __nv_bfloat16*)(sm + QOFF);

    const int tid = threadIdx.x, wid = tid >> 5, lane = tid & 31;
    const int g = lane >> 2, tg = lane & 3;
    const int bh = blockIdx.x;
    const int b = bh >> 4, h = bh & 15;
    const int q0 = blockIdx.y * 32;
    const int wq = wid & 1;             // 2 q-groups of 16
    const int wk = wid >> 1;            // 8 k/d-groups

    const __nv_bfloat16* qHp = qhH + ((size_t)b * LL + q0) * DD + h * DK;
    const __nv_bfloat16* qLp = qhL + ((size_t)b * LL + q0) * DD + h * DK;
    const __nv_bfloat16* kHp = khH + (size_t)b * LL * DD + h * DK;
    const __nv_bfloat16* kLp = khL + (size_t)b * LL * DD + h * DK;
    const float* vhp = vh + (size_t)b * LL * DD + h * DK;
    float* attnBase = attn + ((size_t)bh * LL + q0) * LL;

    // ---- load Q planes (1 cp16 per thread) + prefetch K chunk 0 ----
    {
        int p = tid >> 8, rem = tid & 255, row = rem >> 3, c8 = rem & 7;
        cp16(smb + QOFF + p * 4608 + row * 144 + c8 * 16,
             (p ? qLp : qHp) + (size_t)row * DD + c8 * 8);
    }
#pragma unroll
    for (int j = 0; j < 4; j++) {
        int idx = tid + 512 * j;         // 0..2047
        int p = idx >> 10, rem = idx & 1023, row = rem >> 3, c8 = rem & 7;
        cp16(smb + KOFF + p * 18432 + row * 144 + c8 * 16,
             (p ? kLp : kHp) + (size_t)row * DD + c8 * 8);
    }
    CP_COMMIT;

    // ---- S = Q K^T over 8 double-buffered chunks of 128 k-rows ----
    for (int kc = 0; kc < 8; kc++) {
        if (kc < 7) {
#pragma unroll
            for (int j = 0; j < 4; j++) {
                int idx = tid + 512 * j;
                int p = idx >> 10, rem = idx & 1023, row = rem >> 3, c8 = rem & 7;
                cp16(smb + KOFF + ((kc + 1) & 1) * KBUF + p * 18432 + row * 144 + c8 * 16,
                     (p ? kLp : kHp) + (size_t)((kc + 1) * 128 + row) * DD + h * 0 + c8 * 8);
            }
            CP_COMMIT;
            CP_WAIT1;
        } else {
            CP_WAIT0;
        }
        __syncthreads();

        const __nv_bfloat16* Kb = (const __nv_bfloat16*)(sm + KOFF + (kc & 1) * KBUF);
        float sacc[2][4];
#pragma unroll
        for (int ni = 0; ni < 2; ni++)
#pragma unroll
            for (int r = 0; r < 4; r++) sacc[ni][r] = 0.f;

#pragma unroll
        for (int ks = 0; ks < 4; ks++) {
            uint32_t a_h[4], a_l[4], b_h[2][2], b_l[2][2];
            const __nv_bfloat16* qp = Qh + (wq * 16 + g) * 72 + ks * 16 + 2 * tg;
            a_h[0] = *(const uint32_t*)(qp);
            a_h[1] = *(const uint32_t*)(qp + 8 * 72);
            a_h[2] = *(const uint32_t*)(qp + 8);
            a_h[3] = *(const uint32_t*)(qp + 8 * 72 + 8);
            a_l[0] = *(const uint32_t*)(qp + 2304);
            a_l[1] = *(const uint32_t*)(qp + 2304 + 8 * 72);
            a_l[2] = *(const uint32_t*)(qp + 2304 + 8);
            a_l[3] = *(const uint32_t*)(qp + 2304 + 8 * 72 + 8);
#pragma unroll
            for (int ni = 0; ni < 2; ni++) {
                const __nv_bfloat16* kp = Kb + (wk * 16 + ni * 8 + g) * 72 + ks * 16 + 2 * tg;
                b_h[ni][0] = *(const uint32_t*)(kp);
                b_h[ni][1] = *(const uint32_t*)(kp + 8);
                b_l[ni][0] = *(const uint32_t*)(kp + KPLE);
                b_l[ni][1] = *(const uint32_t*)(kp + KPLE + 8);
            }
#pragma unroll
            for (int ni = 0; ni < 2; ni++) {
                mma_bf16(sacc[ni], a_h, b_h[ni]);
                mma_bf16(sacc[ni], a_h, b_l[ni]);
                mma_bf16(sacc[ni], a_l, b_h[ni]);
            }
        }
#pragma unroll
        for (int ni = 0; ni < 2; ni++) {
            int c = kc * 128 + wk * 16 + ni * 8 + 2 * tg;
            *(float2*)&S[(wq * 16 + g) * SSTR + c]     = make_float2(sacc[ni][0], sacc[ni][1]);
            *(float2*)&S[(wq * 16 + g + 8) * SSTR + c] = make_float2(sacc[ni][2], sacc[ni][3]);
        }
        __syncthreads();
    }

    // prefetch V chunk 0 into buf0 (K data dead)
#pragma unroll
    for (int j = 0; j < 4; j++) {
        int idx = tid + 512 * j;          // 0..2047
        int row = idx >> 4, c4 = idx & 15;
        cp16(smb + KOFF + row * 272 + c4 * 16, vhp + (size_t)row * DD + c4 * 4);
    }
    CP_COMMIT;

    // ---- mask + softmax (2 rows/warp) + write attn ----
#pragma unroll
    for (int rr = 0; rr < 2; rr++) {
        int r = wid * 2 + rr;
        float* Sr = S + r * SSTR;
        const int* mr = mask + ((size_t)b * LL + q0 + r) * LL;
        float m = -1e30f;
        for (int c = lane; c < 1024; c += 32) {
            float s = Sr[c];
            if (mr[c]) s = -1e30f;
            Sr[c] = s;
            m = fmaxf(m, s);
        }
#pragma unroll
        for (int o = 16; o; o >>= 1) m = fmaxf(m, __shfl_xor_sync(0xffffffffu, m, o));
        float sum = 0.f;
        for (int c = lane; c < 1024; c += 32) {
            float s = Sr[c];
            float e = (s <= -9e29f) ? 0.f : __expf(s - m);
            Sr[c] = e;
            sum += e;
        }
#pragma unroll
        for (int o = 16; o; o >>= 1) sum += __shfl_xor_sync(0xffffffffu, sum, o);
        float inv = 1.f / sum;
        float* dst = attnBase + (size_t)r * LL;
        for (int c = lane; c < 1024; c += 32) {
            float p = Sr[c] * inv;
            Sr[c] = p;
            dst[c] = p;
        }
    }

    // ---- PV: warp tile 16q x 8d, V double-buffered chunks of 128 ----
    float pacc[4] = {0.f, 0.f, 0.f, 0.f};
    for (int vc = 0; vc < 8; vc++) {
        if (vc < 7) {
#pragma unroll
            for (int j = 0; j < 4; j++) {
                int idx = tid + 512 * j;
                int row = idx >> 4, c4 = idx & 15;
                cp16(smb + KOFF + ((vc + 1) & 1) * KBUF + row * 272 + c4 * 16,
                     vhp + (size_t)((vc + 1) * 128 + row) * DD + c4 * 4);
            }
            CP_COMMIT;
            CP_WAIT1;
        } else {
            CP_WAIT0;
        }
        __syncthreads();

        const float* Vs = (const float*)(sm + KOFF + (vc & 1) * KBUF);
        const int vcol = wk * 8 + g;
#pragma unroll
        for (int kk = 0; kk < 16; kk++) {
            unsigned af[4], bf2[2];
            int c = vc * 128 + kk * 8 + tg;
            af[0] = f2tf(S[(wq * 16 + g) * SSTR + c]);
            af[1] = f2tf(S[(wq * 16 + g + 8) * SSTR + c]);
            af[2] = f2tf(S[(wq * 16 + g) * SSTR + c + 4]);
            af[3] = f2tf(S[(wq * 16 + g + 8) * SSTR + c + 4]);
            bf2[0] = __float_as_uint(Vs[(kk * 8 + tg) * 68 + vcol]);
            bf2[1] = __float_as_uint(Vs[(kk * 8 + tg + 4) * 68 + vcol]);
            mma_tf32(pacc, af, bf2);
        }
        __syncthreads();
    }

    {
        int c = h * DK + wk * 8 + 2 * tg;
        size_t r0 = (size_t)b * LL + q0 + wq * 16 + g;
        *(float2*)&ctx[r0 * DD + c]       = make_float2(pacc[0], pacc[1]);
        *(float2*)&ctx[(r0 + 8) * DD + c] = make_float2(pacc[2], pacc[3]);
    }
}

// ---------------------------------------------------------------------------
// LayerNorm(proj + residual) * g + b
// ---------------------------------------------------------------------------
__global__ __launch_bounds__(256) void ln_kernel(
    const float* __restrict__ proj, const float* __restrict__ resid,
    const float* __restrict__ gam, const float* __restrict__ bet,
    float* __restrict__ out)
{
    __shared__ float red[8];
    const int row = blockIdx.x;
    const int tid = threadIdx.x;
    const int c0 = tid * 4;
    const int lane = tid & 31, wid = tid >> 5;

    float4 pv = *(const float4*)(proj + (size_t)row * DD + c0);
    float4 rv = *(const float4*)(resid + (size_t)row * DD + c0);
    float x0 = pv.x + rv.x, x1 = pv.y + rv.y, x2 = pv.z + rv.z, x3 = pv.w + rv.w;

    float s = x0 + x1 + x2 + x3;
#pragma unroll
    for (int o = 16; o; o >>= 1) s += __shfl_xor_sync(0xffffffffu, s, o);
    if (lane == 0) red[wid] = s;
    __syncthreads();
    float tot = (lane < 8) ? red[lane] : 0.f;
#pragma unroll
    for (int o = 4; o; o >>= 1) tot += __shfl_xor_sync(0xffffffffu, tot, o);
    tot = __shfl_sync(0xffffffffu, tot, 0);
    float mean = tot * (1.f / 1024.f);

    float d0 = x0 - mean, d1 = x1 - mean, d2 = x2 - mean, d3 = x3 - mean;
    float sq = d0 * d0 + d1 * d1 + d2 * d2 + d3 * d3;
#pragma unroll
    for (int o = 16; o; o >>= 1) sq += __shfl_xor_sync(0xffffffffu, sq, o);
    __syncthreads();
    if (lane == 0) red[wid] = sq;
    __syncthreads();
    float tot2 = (lane < 8) ? red[lane] : 0.f;
#pragma unroll
    for (int o = 4; o; o >>= 1) tot2 += __shfl_xor_sync(0xffffffffu, tot2, o);
    tot2 = __shfl_sync(0xffffffffu, tot2, 0);
    float k = rsqrtf(tot2 * (1.f / 1024.f) + 1e-5f);

    float4 gv = *(const float4*)(gam + c0);
    float4 bv = *(const float4*)(bet + c0);
    float4 ov;
    ov.x = d0 * k * gv.x + bv.x;
    ov.y = d1 * k * gv.y + bv.y;
    ov.z = d2 * k * gv.z + bv.z;
    ov.w = d3 * k * gv.w + bv.w;
    *(float4*)&out[(size_t)row * DD + c0] = ov;
}

// ---------------------------------------------------------------------------
extern "C" void kernel_launch(void* const* d_in, const int* in_sizes, int n_in,
                              void* d_out, int out_size)
{
    const float* q    = (const float*)d_in[0];
    const float* k    = (const float*)d_in[1];
    const float* v    = (const float*)d_in[2];
    const int*   mask = (const int*)  d_in[3];
    const float* npm  = (const float*)d_in[4];
    const float* Wq   = (const float*)d_in[5];
    const float* bq   = (const float*)d_in[6];
    const float* Wk   = (const float*)d_in[7];
    const float* bk   = (const float*)d_in[8];
    const float* Wv   = (const float*)d_in[9];
    const float* bv   = (const float*)d_in[10];
    const float* Wf   = (const float*)d_in[11];
    const float* bf   = (const float*)d_in[12];
    const float* ln_g = (const float*)d_in[13];
    const float* ln_b = (const float*)d_in[14];

    float* out  = (float*)d_out;                       // (B,L,D)
    float* attn = out + (size_t)BB * LL * DD;          // (B,H,L,L)

    __nv_bfloat16 *qhH, *qhL, *khH, *khL, *asH, *asL, *wsH, *wsL;
    float *vh, *ctx, *proj;
    cudaGetSymbolAddress((void**)&qhH, g_qhH);
    cudaGetSymbolAddress((void**)&qhL, g_qhL);
    cudaGetSymbolAddress((void**)&khH, g_khH);
    cudaGetSymbolAddress((void**)&khL, g_khL);
    cudaGetSymbolAddress((void**)&vh,  g_vh);
    cudaGetSymbolAddress((void**)&ctx, g_ctx);
    cudaGetSymbolAddress((void**)&proj, g_proj);
    cudaGetSymbolAddress((void**)&asH, g_asH);
    cudaGetSymbolAddress((void**)&asL, g_asL);
    cudaGetSymbolAddress((void**)&wsH, g_wsH);
    cudaGetSymbolAddress((void**)&wsL, g_wsL);

    cudaFuncSetAttribute(gemm_bf16, cudaFuncAttributeMaxDynamicSharedMemorySize, GEMM_SMEM);
    cudaFuncSetAttribute(attn_kernel, cudaFuncAttributeMaxDynamicSharedMemorySize, ATT_SMEM);

    const int nA4 = ROWS_TOT * DD / 4;
    const int nW4 = DD * DD / 4;
    dim3 gG(DD / 128, ROWS_TOT / 128);   // (8, 64)

    // Q projection -> bf16 planes (scale 1/8 folded)
    split_bf16<<<(nA4 + 255) / 256, 256>>>(q, asH, asL, nA4);
    split_bf16<<<(nW4 + 255) / 256, 256>>>(Wq, wsH, wsL, nW4);
    gemm_bf16<<<gG, 512, GEMM_SMEM>>>(asH, asL, wsH, wsL, bq, npm, 0.125f,
                                      nullptr, qhH, qhL);
    // K projection -> bf16 planes
    split_bf16<<<(nA4 + 255) / 256, 256>>>(k, asH, asL, nA4);
    split_bf16<<<(nW4 + 255) / 256, 256>>>(Wk, wsH, wsL, nW4);
    gemm_bf16<<<gG, 512, GEMM_SMEM>>>(asH, asL, wsH, wsL, bk, npm, 1.0f,
                                      nullptr, khH, khL);
    // V projection -> fp32
    split_bf16<<<(nA4 + 255) / 256, 256>>>(v, asH, asL, nA4);
    split_bf16<<<(nW4 + 255) / 256, 256>>>(Wv, wsH, wsL, nW4);
    gemm_bf16<<<gG, 512, GEMM_SMEM>>>(asH, asL, wsH, wsL, bv, npm, 1.0f,
                                      vh, nullptr, nullptr);

    // Fused attention: S in smem, attn written once
    attn_kernel<<<dim3(BB * HH, LL / 32), 512, ATT_SMEM>>>(
        qhH, qhL, khH, khL, vh, mask, attn, ctx);

    // Output projection -> fp32, then LN
    split_bf16<<<(nA4 + 255) / 256, 256>>>(ctx, asH, asL, nA4);
    split_bf16<<<(nW4 + 255) / 256, 256>>>(Wf, wsH, wsL, nW4);
    gemm_bf16<<<gG, 512, GEMM_SMEM>>>(asH, asL, wsH, wsL, bf, npm, 1.0f,
                                      proj, nullptr, nullptr);

    ln_kernel<<<ROWS_TOT, 256>>>(proj, q, ln_g, ln_b, out);
}

// round 8
// speedup vs baseline: 1.2986x; 1.1538x over previous
#include <cuda_runtime.h>
#include <cuda_bf16.h>
#include <math.h>
#include <cstdint>

#define BB 8
#define LL 1024
#define DD 1024
#define HH 16
#define DK 64
#define ROWS_TOT (BB*LL)          // 8192

// Scratch (device globals)
__device__ __nv_bfloat16 g_qhH[(size_t)ROWS_TOT * DD];
__device__ __nv_bfloat16 g_qhL[(size_t)ROWS_TOT * DD];
__device__ __nv_bfloat16 g_khH[(size_t)ROWS_TOT * DD];
__device__ __nv_bfloat16 g_khL[(size_t)ROWS_TOT * DD];
__device__ float g_vh [(size_t)ROWS_TOT * DD];
__device__ float g_ctx[(size_t)ROWS_TOT * DD];
__device__ float g_proj[(size_t)ROWS_TOT * DD];
__device__ __nv_bfloat16 g_asH[(size_t)ROWS_TOT * DD];
__device__ __nv_bfloat16 g_asL[(size_t)ROWS_TOT * DD];
__device__ __nv_bfloat16 g_wsH[(size_t)DD * DD];
__device__ __nv_bfloat16 g_wsL[(size_t)DD * DD];

// ---------------------------------------------------------------------------
// helpers
// ---------------------------------------------------------------------------
__device__ __forceinline__ uint32_t smem_u32(const void* p) {
    uint32_t a;
    asm("{ .reg .u64 t; cvta.to.shared.u64 t, %1; cvt.u32.u64 %0, t; }" : "=r"(a) : "l"(p));
    return a;
}
__device__ __forceinline__ void cp16(uint32_t dst, const void* src) {
    asm volatile("cp.async.cg.shared.global [%0], [%1], 16;" :: "r"(dst), "l"(src));
}
#define CP_COMMIT asm volatile("cp.async.commit_group;" ::: "memory")
#define CP_WAIT1  asm volatile("cp.async.wait_group 1;" ::: "memory")
#define CP_WAIT0  asm volatile("cp.async.wait_group 0;" ::: "memory")

__device__ __forceinline__ void mma_bf16(float* c, const uint32_t* a, const uint32_t* b) {
    asm volatile(
        "mma.sync.aligned.m16n8k16.row.col.f32.bf16.bf16.f32 "
        "{%0,%1,%2,%3},{%4,%5,%6,%7},{%8,%9},{%0,%1,%2,%3};"
        : "+f"(c[0]), "+f"(c[1]), "+f"(c[2]), "+f"(c[3])
        : "r"(a[0]), "r"(a[1]), "r"(a[2]), "r"(a[3]), "r"(b[0]), "r"(b[1]));
}
__device__ __forceinline__ unsigned f2tf(float x) {
    unsigned r;
    asm("cvt.rna.tf32.f32 %0, %1;" : "=r"(r) : "f"(x));
    return r;
}
__device__ __forceinline__ void mma_tf32(float c[4], const unsigned a[4], const unsigned b[2]) {
    asm volatile(
        "mma.sync.aligned.m16n8k8.row.col.f32.tf32.tf32.f32 "
        "{%0,%1,%2,%3},{%4,%5,%6,%7},{%8,%9},{%0,%1,%2,%3};"
        : "+f"(c[0]), "+f"(c[1]), "+f"(c[2]), "+f"(c[3])
        : "r"(a[0]), "r"(a[1]), "r"(a[2]), "r"(a[3]), "r"(b[0]), "r"(b[1]));
}

// ---------------------------------------------------------------------------
// bf16 hi/lo split
// ---------------------------------------------------------------------------
__global__ __launch_bounds__(256) void split_bf16(
    const float* __restrict__ x, __nv_bfloat16* __restrict__ hi,
    __nv_bfloat16* __restrict__ lo, int n4)
{
    int i = blockIdx.x * blockDim.x + threadIdx.x;
    if (i >= n4) return;
    float4 v = ((const float4*)x)[i];
    __nv_bfloat16 h0 = __float2bfloat16(v.x);
    __nv_bfloat16 h1 = __float2bfloat16(v.y);
    __nv_bfloat16 h2 = __float2bfloat16(v.z);
    __nv_bfloat16 h3 = __float2bfloat16(v.w);
    __nv_bfloat16 l0 = __float2bfloat16(v.x - __bfloat162float(h0));
    __nv_bfloat16 l1 = __float2bfloat16(v.y - __bfloat162float(h1));
    __nv_bfloat16 l2 = __float2bfloat16(v.z - __bfloat162float(h2));
    __nv_bfloat16 l3 = __float2bfloat16(v.w - __bfloat162float(h3));
    ((__nv_bfloat162*)hi)[i * 2]     = __nv_bfloat162(h0, h1);
    ((__nv_bfloat162*)hi)[i * 2 + 1] = __nv_bfloat162(h2, h3);
    ((__nv_bfloat162*)lo)[i * 2]     = __nv_bfloat162(l0, l1);
    ((__nv_bfloat162*)lo)[i * 2 + 1] = __nv_bfloat162(l2, l3);
}

// f32 -> bf16 convert (no split)
__global__ __launch_bounds__(256) void conv_bf16(
    const float* __restrict__ x, __nv_bfloat16* __restrict__ hi, int n4)
{
    int i = blockIdx.x * blockDim.x + threadIdx.x;
    if (i >= n4) return;
    float4 v = ((const float4*)x)[i];
    ((__nv_bfloat162*)hi)[i * 2]     = __nv_bfloat162(__float2bfloat16(v.x), __float2bfloat16(v.y));
    ((__nv_bfloat162*)hi)[i * 2 + 1] = __nv_bfloat162(__float2bfloat16(v.z), __float2bfloat16(v.w));
}

// ===========================================================================
// 3-term bf16-split GEMM (Q/K projections)
// ===========================================================================
#define PL_E 5120
#define PL_B (PL_E*2)
#define BUF_B (4*PL_B)
#define GEMM_SMEM (2*BUF_B)

__global__ __launch_bounds__(512) void gemm_bf16(
    const __nv_bfloat16* __restrict__ Ah, const __nv_bfloat16* __restrict__ Al,
    const __nv_bfloat16* __restrict__ Bh, const __nv_bfloat16* __restrict__ Bl,
    const float* __restrict__ bias, const float* __restrict__ npm, float scale,
    float* __restrict__ outF, __nv_bfloat16* __restrict__ outH,
    __nv_bfloat16* __restrict__ outL)
{
    extern __shared__ char sm[];
    const uint32_t smb = smem_u32(sm);
    const int tid = threadIdx.x, wid = tid >> 5, lane = tid & 31;
    const int g = lane >> 2, tg = lane & 3;
    const int bm = blockIdx.y * 128, bn = blockIdx.x * 128;
    const int wm = (wid & 1) * 64, wn = (wid >> 1) * 16;

    const __nv_bfloat16* srcs[4] = { Ah + (size_t)bm * DD, Al + (size_t)bm * DD,
                                     Bh + (size_t)bn * DD, Bl + (size_t)bn * DD };
    const int frow = tid >> 2, fc = tid & 3;

    float acc[4][2][4];
#pragma unroll
    for (int mi = 0; mi < 4; mi++)
#pragma unroll
        for (int ni = 0; ni < 2; ni++)
#pragma unroll
            for (int r = 0; r < 4; r++) acc[mi][ni][r] = 0.f;

#pragma unroll
    for (int i = 0; i < 4; i++)
        cp16(smb + i * PL_B + frow * 80 + fc * 16,
             srcs[i] + (size_t)frow * DD + fc * 8);
    CP_COMMIT;

    for (int kt = 0; kt < 32; kt++) {
        if (kt < 31) {
#pragma unroll
            for (int i = 0; i < 4; i++)
                cp16(smb + ((kt + 1) & 1) * BUF_B + i * PL_B + frow * 80 + fc * 16,
                     srcs[i] + (size_t)frow * DD + (kt + 1) * 32 + fc * 8);
            CP_COMMIT;
            CP_WAIT1;
        } else {
            CP_WAIT0;
        }
        __syncthreads();

        const __nv_bfloat16* buf = (const __nv_bfloat16*)(sm + (kt & 1) * BUF_B);
#pragma unroll
        for (int ks = 0; ks < 2; ks++) {
            uint32_t a_h[4][4], a_l[4][4], b_h[2][2], b_l[2][2];
#pragma unroll
            for (int mi = 0; mi < 4; mi++) {
                const __nv_bfloat16* p = buf + (wm + mi * 16 + g) * 40 + ks * 16 + 2 * tg;
                a_h[mi][0] = *(const uint32_t*)(p);
                a_h[mi][1] = *(const uint32_t*)(p + 8 * 40);
                a_h[mi][2] = *(const uint32_t*)(p + 8);
                a_h[mi][3] = *(const uint32_t*)(p + 8 * 40 + 8);
                a_l[mi][0] = *(const uint32_t*)(p + PL_E);
                a_l[mi][1] = *(const uint32_t*)(p + PL_E + 8 * 40);
                a_l[mi][2] = *(const uint32_t*)(p + PL_E + 8);
                a_l[mi][3] = *(const uint32_t*)(p + PL_E + 8 * 40 + 8);
            }
#pragma unroll
            for (int ni = 0; ni < 2; ni++) {
                const __nv_bfloat16* p = buf + 2 * PL_E + (wn + ni * 8 + g) * 40 + ks * 16 + 2 * tg;
                b_h[ni][0] = *(const uint32_t*)(p);
                b_h[ni][1] = *(const uint32_t*)(p + 8);
                b_l[ni][0] = *(const uint32_t*)(p + PL_E);
                b_l[ni][1] = *(const uint32_t*)(p + PL_E + 8);
            }
#pragma unroll
            for (int mi = 0; mi < 4; mi++)
#pragma unroll
                for (int ni = 0; ni < 2; ni++) {
                    mma_bf16(acc[mi][ni], a_h[mi], b_h[ni]);
                    mma_bf16(acc[mi][ni], a_h[mi], b_l[ni]);
                    mma_bf16(acc[mi][ni], a_l[mi], b_h[ni]);
                }
        }
        __syncthreads();
    }

#pragma unroll
    for (int mi = 0; mi < 4; mi++) {
        int r0 = bm + wm + mi * 16 + g, r1 = r0 + 8;
        float nv0 = npm[r0] * scale, nv1 = npm[r1] * scale;
#pragma unroll
        for (int ni = 0; ni < 2; ni++) {
            int c0 = bn + wn + ni * 8 + 2 * tg;
            float b0 = bias[c0], b1 = bias[c0 + 1];
            float v00 = (acc[mi][ni][0] + b0) * nv0, v01 = (acc[mi][ni][1] + b1) * nv0;
            float v10 = (acc[mi][ni][2] + b0) * nv1, v11 = (acc[mi][ni][3] + b1) * nv1;
            if (outF) {
                *(float2*)&outF[(size_t)r0 * DD + c0] = make_float2(v00, v01);
                *(float2*)&outF[(size_t)r1 * DD + c0] = make_float2(v10, v11);
            } else {
                __nv_bfloat16 h00 = __float2bfloat16(v00), h01 = __float2bfloat16(v01);
                __nv_bfloat16 h10 = __float2bfloat16(v10), h11 = __float2bfloat16(v11);
                *(__nv_bfloat162*)&outH[(size_t)r0 * DD + c0] = __nv_bfloat162(h00, h01);
                *(__nv_bfloat162*)&outH[(size_t)r1 * DD + c0] = __nv_bfloat162(h10, h11);
                *(__nv_bfloat162*)&outL[(size_t)r0 * DD + c0] = __nv_bfloat162(
                    __float2bfloat16(v00 - __bfloat162float(h00)),
                    __float2bfloat16(v01 - __bfloat162float(h01)));
                *(__nv_bfloat162*)&outL[(size_t)r1 * DD + c0] = __nv_bfloat162(
                    __float2bfloat16(v10 - __bfloat162float(h10)),
                    __float2bfloat16(v11 - __bfloat162float(h11)));
            }
        }
    }
}

// ===========================================================================
// single-term bf16 GEMM (V / output projections): C = (A@W^T + bias)*npm*scale
// 128x128 tile, BK=32, 512 threads; smem 2 buf x 2 planes x 10240 = 40960 B
// ===========================================================================
#define BUF1_B (2*PL_B)
#define GEMM1_SMEM (2*BUF1_B)

__global__ __launch_bounds__(512) void gemm_bf16_1t(
    const __nv_bfloat16* __restrict__ A, const __nv_bfloat16* __restrict__ B,
    const float* __restrict__ bias, const float* __restrict__ npm, float scale,
    float* __restrict__ outF)
{
    extern __shared__ char sm[];
    const uint32_t smb = smem_u32(sm);
    const int tid = threadIdx.x, wid = tid >> 5, lane = tid & 31;
    const int g = lane >> 2, tg = lane & 3;
    const int bm = blockIdx.y * 128, bn = blockIdx.x * 128;
    const int wm = (wid & 1) * 64, wn = (wid >> 1) * 16;

    const __nv_bfloat16* srcs[2] = { A + (size_t)bm * DD, B + (size_t)bn * DD };
    const int frow = tid >> 2, fc = tid & 3;

    float acc[4][2][4];
#pragma unroll
    for (int mi = 0; mi < 4; mi++)
#pragma unroll
        for (int ni = 0; ni < 2; ni++)
#pragma unroll
            for (int r = 0; r < 4; r++) acc[mi][ni][r] = 0.f;

#pragma unroll
    for (int i = 0; i < 2; i++)
        cp16(smb + i * PL_B + frow * 80 + fc * 16,
             srcs[i] + (size_t)frow * DD + fc * 8);
    CP_COMMIT;

    for (int kt = 0; kt < 32; kt++) {
        if (kt < 31) {
#pragma unroll
            for (int i = 0; i < 2; i++)
                cp16(smb + ((kt + 1) & 1) * BUF1_B + i * PL_B + frow * 80 + fc * 16,
                     srcs[i] + (size_t)frow * DD + (kt + 1) * 32 + fc * 8);
            CP_COMMIT;
            CP_WAIT1;
        } else {
            CP_WAIT0;
        }
        __syncthreads();

        const __nv_bfloat16* buf = (const __nv_bfloat16*)(sm + (kt & 1) * BUF1_B);
#pragma unroll
        for (int ks = 0; ks < 2; ks++) {
            uint32_t a_h[4][4], b_h[2][2];
#pragma unroll
            for (int mi = 0; mi < 4; mi++) {
                const __nv_bfloat16* p = buf + (wm + mi * 16 + g) * 40 + ks * 16 + 2 * tg;
                a_h[mi][0] = *(const uint32_t*)(p);
                a_h[mi][1] = *(const uint32_t*)(p + 8 * 40);
                a_h[mi][2] = *(const uint32_t*)(p + 8);
                a_h[mi][3] = *(const uint32_t*)(p + 8 * 40 + 8);
            }
#pragma unroll
            for (int ni = 0; ni < 2; ni++) {
                const __nv_bfloat16* p = buf + PL_E + (wn + ni * 8 + g) * 40 + ks * 16 + 2 * tg;
                b_h[ni][0] = *(const uint32_t*)(p);
                b_h[ni][1] = *(const uint32_t*)(p + 8);
            }
#pragma unroll
            for (int mi = 0; mi < 4; mi++)
#pragma unroll
                for (int ni = 0; ni < 2; ni++)
                    mma_bf16(acc[mi][ni], a_h[mi], b_h[ni]);
        }
        __syncthreads();
    }

#pragma unroll
    for (int mi = 0; mi < 4; mi++) {
        int r0 = bm + wm + mi * 16 + g, r1 = r0 + 8;
        float nv0 = npm[r0] * scale, nv1 = npm[r1] * scale;
#pragma unroll
        for (int ni = 0; ni < 2; ni++) {
            int c0 = bn + wn + ni * 8 + 2 * tg;
            float b0 = bias[c0], b1 = bias[c0 + 1];
            *(float2*)&outF[(size_t)r0 * DD + c0] =
                make_float2((acc[mi][ni][0] + b0) * nv0, (acc[mi][ni][1] + b1) * nv0);
            *(float2*)&outF[(size_t)r1 * DD + c0] =
                make_float2((acc[mi][ni][2] + b0) * nv1, (acc[mi][ni][3] + b1) * nv1);
        }
    }
}

// ===========================================================================
// Fused attention (R7, proven): block = (b,h) x 32 q-rows, 512 threads
// ===========================================================================
#define SSTR 1028
#define QOFF 131584
#define KOFF (QOFF + 9216)
#define KBUF 36864
#define KPLE 9216
#define ATT_SMEM (KOFF + 2*KBUF)        // 214528

__global__ __launch_bounds__(512) void attn_kernel(
    const __nv_bfloat16* __restrict__ qhH, const __nv_bfloat16* __restrict__ qhL,
    const __nv_bfloat16* __restrict__ khH, const __nv_bfloat16* __restrict__ khL,
    const float* __restrict__ vh, const int* __restrict__ mask,
    float* __restrict__ attn, float* __restrict__ ctx)
{
    extern __shared__ char sm[];
    const uint32_t smb = smem_u32(sm);
    float* S = (float*)sm;
    const __nv_bfloat16* Qh = (const __nv_bfloat16*)(sm + QOFF);

    const int tid = threadIdx.x, wid = tid >> 5, lane = tid & 31;
    const int g = lane >> 2, tg = lane & 3;
    const int bh = blockIdx.x;
    const int b = bh >> 4, h = bh & 15;
    const int q0 = blockIdx.y * 32;
    const int wq = wid & 1;
    const int wk = wid >> 1;

    const __nv_bfloat16* qHp = qhH + ((size_t)b * LL + q0) * DD + h * DK;
    const __nv_bfloat16* qLp = qhL + ((size_t)b * LL + q0) * DD + h * DK;
    const __nv_bfloat16* kHp = khH + (size_t)b * LL * DD + h * DK;
    const __nv_bfloat16* kLp = khL + (size_t)b * LL * DD + h * DK;
    const float* vhp = vh + (size_t)b * LL * DD + h * DK;
    float* attnBase = attn + ((size_t)bh * LL + q0) * LL;

    {
        int p = tid >> 8, rem = tid & 255, row = rem >> 3, c8 = rem & 7;
        cp16(smb + QOFF + p * 4608 + row * 144 + c8 * 16,
             (p ? qLp : qHp) + (size_t)row * DD + c8 * 8);
    }
#pragma unroll
    for (int j = 0; j < 4; j++) {
        int idx = tid + 512 * j;
        int p = idx >> 10, rem = idx & 1023, row = rem >> 3, c8 = rem & 7;
        cp16(smb + KOFF + p * 18432 + row * 144 + c8 * 16,
             (p ? kLp : kHp) + (size_t)row * DD + c8 * 8);
    }
    CP_COMMIT;

    for (int kc = 0; kc < 8; kc++) {
        if (kc < 7) {
#pragma unroll
            for (int j = 0; j < 4; j++) {
                int idx = tid + 512 * j;
                int p = idx >> 10, rem = idx & 1023, row = rem >> 3, c8 = rem & 7;
                cp16(smb + KOFF + ((kc + 1) & 1) * KBUF + p * 18432 + row * 144 + c8 * 16,
                     (p ? kLp : kHp) + (size_t)((kc + 1) * 128 + row) * DD + c8 * 8);
            }
            CP_COMMIT;
            CP_WAIT1;
        } else {
            CP_WAIT0;
        }
        __syncthreads();

        const __nv_bfloat16* Kb = (const __nv_bfloat16*)(sm + KOFF + (kc & 1) * KBUF);
        float sacc[2][4];
#pragma unroll
        for (int ni = 0; ni < 2; ni++)
#pragma unroll
            for (int r = 0; r < 4; r++) sacc[ni][r] = 0.f;

#pragma unroll
        for (int ks = 0; ks < 4; ks++) {
            uint32_t a_h[4], a_l[4], b_h[2][2], b_l[2][2];
            const __nv_bfloat16* qp = Qh + (wq * 16 + g) * 72 + ks * 16 + 2 * tg;
            a_h[0] = *(const uint32_t*)(qp);
            a_h[1] = *(const uint32_t*)(qp + 8 * 72);
            a_h[2] = *(const uint32_t*)(qp + 8);
            a_h[3] = *(const uint32_t*)(qp + 8 * 72 + 8);
            a_l[0] = *(const uint32_t*)(qp + 2304);
            a_l[1] = *(const uint32_t*)(qp + 2304 + 8 * 72);
            a_l[2] = *(const uint32_t*)(qp + 2304 + 8);
            a_l[3] = *(const uint32_t*)(qp + 2304 + 8 * 72 + 8);
#pragma unroll
            for (int ni = 0; ni < 2; ni++) {
                const __nv_bfloat16* kp = Kb + (wk * 16 + ni * 8 + g) * 72 + ks * 16 + 2 * tg;
                b_h[ni][0] = *(const uint32_t*)(kp);
                b_h[ni][1] = *(const uint32_t*)(kp + 8);
                b_l[ni][0] = *(const uint32_t*)(kp + KPLE);
                b_l[ni][1] = *(const uint32_t*)(kp + KPLE + 8);
            }
#pragma unroll
            for (int ni = 0; ni < 2; ni++) {
                mma_bf16(sacc[ni], a_h, b_h[ni]);
                mma_bf16(sacc[ni], a_h, b_l[ni]);
                mma_bf16(sacc[ni], a_l, b_h[ni]);
            }
        }
#pragma unroll
        for (int ni = 0; ni < 2; ni++) {
            int c = kc * 128 + wk * 16 + ni * 8 + 2 * tg;
            *(float2*)&S[(wq * 16 + g) * SSTR + c]     = make_float2(sacc[ni][0], sacc[ni][1]);
            *(float2*)&S[(wq * 16 + g + 8) * SSTR + c] = make_float2(sacc[ni][2], sacc[ni][3]);
        }
        __syncthreads();
    }

#pragma unroll
    for (int j = 0; j < 4; j++) {
        int idx = tid + 512 * j;
        int row = idx >> 4, c4 = idx & 15;
        cp16(smb + KOFF + row * 272 + c4 * 16, vhp + (size_t)row * DD + c4 * 4);
    }
    CP_COMMIT;

#pragma unroll
    for (int rr = 0; rr < 2; rr++) {
        int r = wid * 2 + rr;
        float* Sr = S + r * SSTR;
        const int* mr = mask + ((size_t)b * LL + q0 + r) * LL;
        float m = -1e30f;
        for (int c = lane; c < 1024; c += 32) {
            float s = Sr[c];
            if (mr[c]) s = -1e30f;
            Sr[c] = s;
            m = fmaxf(m, s);
        }
#pragma unroll
        for (int o = 16; o; o >>= 1) m = fmaxf(m, __shfl_xor_sync(0xffffffffu, m, o));
        float sum = 0.f;
        for (int c = lane; c < 1024; c += 32) {
            float s = Sr[c];
            float e = (s <= -9e29f) ? 0.f : __expf(s - m);
            Sr[c] = e;
            sum += e;
        }
#pragma unroll
        for (int o = 16; o; o >>= 1) sum += __shfl_xor_sync(0xffffffffu, sum, o);
        float inv = 1.f / sum;
        float* dst = attnBase + (size_t)r * LL;
        for (int c = lane; c < 1024; c += 32) {
            float p = Sr[c] * inv;
            Sr[c] = p;
            dst[c] = p;
        }
    }

    float pacc[4] = {0.f, 0.f, 0.f, 0.f};
    for (int vc = 0; vc < 8; vc++) {
        if (vc < 7) {
#pragma unroll
            for (int j = 0; j < 4; j++) {
                int idx = tid + 512 * j;
                int row = idx >> 4, c4 = idx & 15;
                cp16(smb + KOFF + ((vc + 1) & 1) * KBUF + row * 272 + c4 * 16,
                     vhp + (size_t)((vc + 1) * 128 + row) * DD + c4 * 4);
            }
            CP_COMMIT;
            CP_WAIT1;
        } else {
            CP_WAIT0;
        }
        __syncthreads();

        const float* Vs = (const float*)(sm + KOFF + (vc & 1) * KBUF);
        const int vcol = wk * 8 + g;
#pragma unroll
        for (int kk = 0; kk < 16; kk++) {
            unsigned af[4], bf2[2];
            int c = vc * 128 + kk * 8 + tg;
            af[0] = f2tf(S[(wq * 16 + g) * SSTR + c]);
            af[1] = f2tf(S[(wq * 16 + g + 8) * SSTR + c]);
            af[2] = f2tf(S[(wq * 16 + g) * SSTR + c + 4]);
            af[3] = f2tf(S[(wq * 16 + g + 8) * SSTR + c + 4]);
            bf2[0] = __float_as_uint(Vs[(kk * 8 + tg) * 68 + vcol]);
            bf2[1] = __float_as_uint(Vs[(kk * 8 + tg + 4) * 68 + vcol]);
            mma_tf32(pacc, af, bf2);
        }
        __syncthreads();
    }

    {
        int c = h * DK + wk * 8 + 2 * tg;
        size_t r0 = (size_t)b * LL + q0 + wq * 16 + g;
        *(float2*)&ctx[r0 * DD + c]       = make_float2(pacc[0], pacc[1]);
        *(float2*)&ctx[(r0 + 8) * DD + c] = make_float2(pacc[2], pacc[3]);
    }
}

// ---------------------------------------------------------------------------
// LayerNorm(proj + residual) * g + b
// ---------------------------------------------------------------------------
__global__ __launch_bounds__(256) void ln_kernel(
    const float* __restrict__ proj, const float* __restrict__ resid,
    const float* __restrict__ gam, const float* __restrict__ bet,
    float* __restrict__ out)
{
    __shared__ float red[8];
    const int row = blockIdx.x;
    const int tid = threadIdx.x;
    const int c0 = tid * 4;
    const int lane = tid & 31, wid = tid >> 5;

    float4 pv = *(const float4*)(proj + (size_t)row * DD + c0);
    float4 rv = *(const float4*)(resid + (size_t)row * DD + c0);
    float x0 = pv.x + rv.x, x1 = pv.y + rv.y, x2 = pv.z + rv.z, x3 = pv.w + rv.w;

    float s = x0 + x1 + x2 + x3;
#pragma unroll
    for (int o = 16; o; o >>= 1) s += __shfl_xor_sync(0xffffffffu, s, o);
    if (lane == 0) red[wid] = s;
    __syncthreads();
    float tot = (lane < 8) ? red[lane] : 0.f;
#pragma unroll
    for (int o = 4; o; o >>= 1) tot += __shfl_xor_sync(0xffffffffu, tot, o);
    tot = __shfl_sync(0xffffffffu, tot, 0);
    float mean = tot * (1.f / 1024.f);

    float d0 = x0 - mean, d1 = x1 - mean, d2 = x2 - mean, d3 = x3 - mean;
    float sq = d0 * d0 + d1 * d1 + d2 * d2 + d3 * d3;
#pragma unroll
    for (int o = 16; o; o >>= 1) sq += __shfl_xor_sync(0xffffffffu, sq, o);
    __syncthreads();
    if (lane == 0) red[wid] = sq;
    __syncthreads();
    float tot2 = (lane < 8) ? red[lane] : 0.f;
#pragma unroll
    for (int o = 4; o; o >>= 1) tot2 += __shfl_xor_sync(0xffffffffu, tot2, o);
    tot2 = __shfl_sync(0xffffffffu, tot2, 0);
    float k = rsqrtf(tot2 * (1.f / 1024.f) + 1e-5f);

    float4 gv = *(const float4*)(gam + c0);
    float4 bv = *(const float4*)(bet + c0);
    float4 ov;
    ov.x = d0 * k * gv.x + bv.x;
    ov.y = d1 * k * gv.y + bv.y;
    ov.z = d2 * k * gv.z + bv.z;
    ov.w = d3 * k * gv.w + bv.w;
    *(float4*)&out[(size_t)row * DD + c0] = ov;
}

// ---------------------------------------------------------------------------
extern "C" void kernel_launch(void* const* d_in, const int* in_sizes, int n_in,
                              void* d_out, int out_size)
{
    const float* q    = (const float*)d_in[0];
    const float* k    = (const float*)d_in[1];
    const float* v    = (const float*)d_in[2];
    const int*   mask = (const int*)  d_in[3];
    const float* npm  = (const float*)d_in[4];
    const float* Wq   = (const float*)d_in[5];
    const float* bq   = (const float*)d_in[6];
    const float* Wk   = (const float*)d_in[7];
    const float* bk   = (const float*)d_in[8];
    const float* Wv   = (const float*)d_in[9];
    const float* bv   = (const float*)d_in[10];
    const float* Wf   = (const float*)d_in[11];
    const float* bf   = (const float*)d_in[12];
    const float* ln_g = (const float*)d_in[13];
    const float* ln_b = (const float*)d_in[14];

    float* out  = (float*)d_out;
    float* attn = out + (size_t)BB * LL * DD;

    __nv_bfloat16 *qhH, *qhL, *khH, *khL, *asH, *asL, *wsH, *wsL;
    float *vh, *ctx, *proj;
    cudaGetSymbolAddress((void**)&qhH, g_qhH);
    cudaGetSymbolAddress((void**)&qhL, g_qhL);
    cudaGetSymbolAddress((void**)&khH, g_khH);
    cudaGetSymbolAddress((void**)&khL, g_khL);
    cudaGetSymbolAddress((void**)&vh,  g_vh);
    cudaGetSymbolAddress((void**)&ctx, g_ctx);
    cudaGetSymbolAddress((void**)&proj, g_proj);
    cudaGetSymbolAddress((void**)&asH, g_asH);
    cudaGetSymbolAddress((void**)&asL, g_asL);
    cudaGetSymbolAddress((void**)&wsH, g_wsH);
    cudaGetSymbolAddress((void**)&wsL, g_wsL);

    cudaFuncSetAttribute(gemm_bf16, cudaFuncAttributeMaxDynamicSharedMemorySize, GEMM_SMEM);
    cudaFuncSetAttribute(gemm_bf16_1t, cudaFuncAttributeMaxDynamicSharedMemorySize, GEMM1_SMEM);
    cudaFuncSetAttribute(attn_kernel, cudaFuncAttributeMaxDynamicSharedMemorySize, ATT_SMEM);

    const int nA4 = ROWS_TOT * DD / 4;
    const int nW4 = DD * DD / 4;
    dim3 gG(DD / 128, ROWS_TOT / 128);   // (8, 64)

    // Q projection -> bf16 planes (scale 1/8 folded), 3-term
    split_bf16<<<(nA4 + 255) / 256, 256>>>(q, asH, asL, nA4);
    split_bf16<<<(nW4 + 255) / 256, 256>>>(Wq, wsH, wsL, nW4);
    gemm_bf16<<<gG, 512, GEMM_SMEM>>>(asH, asL, wsH, wsL, bq, npm, 0.125f,
                                      nullptr, qhH, qhL);
    // K projection -> bf16 planes, 3-term
    split_bf16<<<(nA4 + 255) / 256, 256>>>(k, asH, asL, nA4);
    split_bf16<<<(nW4 + 255) / 256, 256>>>(Wk, wsH, wsL, nW4);
    gemm_bf16<<<gG, 512, GEMM_SMEM>>>(asH, asL, wsH, wsL, bk, npm, 1.0f,
                                      nullptr, khH, khL);
    // V projection -> fp32, single-term bf16
    conv_bf16<<<(nA4 + 255) / 256, 256>>>(v, asH, nA4);
    conv_bf16<<<(nW4 + 255) / 256, 256>>>(Wv, wsH, nW4);
    gemm_bf16_1t<<<gG, 512, GEMM1_SMEM>>>(asH, wsH, bv, npm, 1.0f, vh);

    // Fused attention
    attn_kernel<<<dim3(BB * HH, LL / 32), 512, ATT_SMEM>>>(
        qhH, qhL, khH, khL, vh, mask, attn, ctx);

    // Output projection -> fp32, single-term bf16, then LN
    conv_bf16<<<(nA4 + 255) / 256, 256>>>(ctx, asH, nA4);
    conv_bf16<<<(nW4 + 255) / 256, 256>>>(Wf, wsH, nW4);
    gemm_bf16_1t<<<gG, 512, GEMM1_SMEM>>>(asH, wsH, bf, npm, 1.0f, proj);

    ln_kernel<<<ROWS_TOT, 256>>>(proj, q, ln_g, ln_b, out);
}

// round 9
// speedup vs baseline: 1.4071x; 1.0835x over previous
#include <cuda_runtime.h>
#include <cuda_fp16.h>
#include <math.h>
#include <cstdint>

#define BB 8
#define LL 1024
#define DD 1024
#define HH 16
#define DK 64
#define ROWS_TOT (BB*LL)          // 8192

// Scratch (device globals)
__device__ __half g_qhH[(size_t)ROWS_TOT * DD];
__device__ __half g_qhL[(size_t)ROWS_TOT * DD];
__device__ __half g_khH[(size_t)ROWS_TOT * DD];
__device__ __half g_khL[(size_t)ROWS_TOT * DD];
__device__ __half g_vhT[(size_t)ROWS_TOT * DD];   // [b][h][d][token] fp16
__device__ __half g_ctx[(size_t)ROWS_TOT * DD];   // fp16
__device__ float  g_proj[(size_t)ROWS_TOT * DD];
__device__ __half g_asH[(size_t)ROWS_TOT * DD];
__device__ __half g_asL[(size_t)ROWS_TOT * DD];
__device__ __half g_wsH[(size_t)DD * DD];
__device__ __half g_wsL[(size_t)DD * DD];

// ---------------------------------------------------------------------------
// helpers
// ---------------------------------------------------------------------------
__device__ __forceinline__ uint32_t smem_u32(const void* p) {
    uint32_t a;
    asm("{ .reg .u64 t; cvta.to.shared.u64 t, %1; cvt.u32.u64 %0, t; }" : "=r"(a) : "l"(p));
    return a;
}
__device__ __forceinline__ void cp16(uint32_t dst, const void* src) {
    asm volatile("cp.async.cg.shared.global [%0], [%1], 16;" :: "r"(dst), "l"(src));
}
#define CP_COMMIT asm volatile("cp.async.commit_group;" ::: "memory")
#define CP_WAIT1  asm volatile("cp.async.wait_group 1;" ::: "memory")
#define CP_WAIT0  asm volatile("cp.async.wait_group 0;" ::: "memory")

__device__ __forceinline__ void mma_f16(float* c, const uint32_t* a, const uint32_t* b) {
    asm volatile(
        "mma.sync.aligned.m16n8k16.row.col.f32.f16.f16.f32 "
        "{%0,%1,%2,%3},{%4,%5,%6,%7},{%8,%9},{%0,%1,%2,%3};"
        : "+f"(c[0]), "+f"(c[1]), "+f"(c[2]), "+f"(c[3])
        : "r"(a[0]), "r"(a[1]), "r"(a[2]), "r"(a[3]), "r"(b[0]), "r"(b[1]));
}

// ---------------------------------------------------------------------------
// fp16 hi/lo split & convert
// ---------------------------------------------------------------------------
__global__ __launch_bounds__(256) void split_f16(
    const float* __restrict__ x, __half* __restrict__ hi,
    __half* __restrict__ lo, int n4)
{
    int i = blockIdx.x * blockDim.x + threadIdx.x;
    if (i >= n4) return;
    float4 v = ((const float4*)x)[i];
    __half h0 = __float2half(v.x), h1 = __float2half(v.y);
    __half h2 = __float2half(v.z), h3 = __float2half(v.w);
    __half l0 = __float2half(v.x - __half2float(h0));
    __half l1 = __float2half(v.y - __half2float(h1));
    __half l2 = __float2half(v.z - __half2float(h2));
    __half l3 = __float2half(v.w - __half2float(h3));
    ((__half2*)hi)[i * 2]     = __halves2half2(h0, h1);
    ((__half2*)hi)[i * 2 + 1] = __halves2half2(h2, h3);
    ((__half2*)lo)[i * 2]     = __halves2half2(l0, l1);
    ((__half2*)lo)[i * 2 + 1] = __halves2half2(l2, l3);
}

__global__ __launch_bounds__(256) void conv_f16(
    const float* __restrict__ x, __half* __restrict__ hi, int n4)
{
    int i = blockIdx.x * blockDim.x + threadIdx.x;
    if (i >= n4) return;
    float4 v = ((const float4*)x)[i];
    ((__half2*)hi)[i * 2]     = __floats2half2_rn(v.x, v.y);
    ((__half2*)hi)[i * 2 + 1] = __floats2half2_rn(v.z, v.w);
}

// ===========================================================================
// 3-term fp16-split GEMM (Q/K projections) -> fp16 hi/lo plane outputs
// ===========================================================================
#define PL_E 5120
#define PL_B (PL_E*2)
#define BUF_B (4*PL_B)
#define GEMM_SMEM (2*BUF_B)

__global__ __launch_bounds__(512) void gemm_f16_3t(
    const __half* __restrict__ Ah, const __half* __restrict__ Al,
    const __half* __restrict__ Bh, const __half* __restrict__ Bl,
    const float* __restrict__ bias, const float* __restrict__ npm, float scale,
    __half* __restrict__ outH, __half* __restrict__ outL)
{
    extern __shared__ char sm[];
    const uint32_t smb = smem_u32(sm);
    const int tid = threadIdx.x, wid = tid >> 5, lane = tid & 31;
    const int g = lane >> 2, tg = lane & 3;
    const int bm = blockIdx.y * 128, bn = blockIdx.x * 128;
    const int wm = (wid & 1) * 64, wn = (wid >> 1) * 16;

    const __half* srcs[4] = { Ah + (size_t)bm * DD, Al + (size_t)bm * DD,
                              Bh + (size_t)bn * DD, Bl + (size_t)bn * DD };
    const int frow = tid >> 2, fc = tid & 3;

    float acc[4][2][4];
#pragma unroll
    for (int mi = 0; mi < 4; mi++)
#pragma unroll
        for (int ni = 0; ni < 2; ni++)
#pragma unroll
            for (int r = 0; r < 4; r++) acc[mi][ni][r] = 0.f;

#pragma unroll
    for (int i = 0; i < 4; i++)
        cp16(smb + i * PL_B + frow * 80 + fc * 16, srcs[i] + (size_t)frow * DD + fc * 8);
    CP_COMMIT;

    for (int kt = 0; kt < 32; kt++) {
        if (kt < 31) {
#pragma unroll
            for (int i = 0; i < 4; i++)
                cp16(smb + ((kt + 1) & 1) * BUF_B + i * PL_B + frow * 80 + fc * 16,
                     srcs[i] + (size_t)frow * DD + (kt + 1) * 32 + fc * 8);
            CP_COMMIT;
            CP_WAIT1;
        } else {
            CP_WAIT0;
        }
        __syncthreads();

        const __half* buf = (const __half*)(sm + (kt & 1) * BUF_B);
#pragma unroll
        for (int ks = 0; ks < 2; ks++) {
            uint32_t a_h[4][4], a_l[4][4], b_h[2][2], b_l[2][2];
#pragma unroll
            for (int mi = 0; mi < 4; mi++) {
                const __half* p = buf + (wm + mi * 16 + g) * 40 + ks * 16 + 2 * tg;
                a_h[mi][0] = *(const uint32_t*)(p);
                a_h[mi][1] = *(const uint32_t*)(p + 8 * 40);
                a_h[mi][2] = *(const uint32_t*)(p + 8);
                a_h[mi][3] = *(const uint32_t*)(p + 8 * 40 + 8);
                a_l[mi][0] = *(const uint32_t*)(p + PL_E);
                a_l[mi][1] = *(const uint32_t*)(p + PL_E + 8 * 40);
                a_l[mi][2] = *(const uint32_t*)(p + PL_E + 8);
                a_l[mi][3] = *(const uint32_t*)(p + PL_E + 8 * 40 + 8);
            }
#pragma unroll
            for (int ni = 0; ni < 2; ni++) {
                const __half* p = buf + 2 * PL_E + (wn + ni * 8 + g) * 40 + ks * 16 + 2 * tg;
                b_h[ni][0] = *(const uint32_t*)(p);
                b_h[ni][1] = *(const uint32_t*)(p + 8);
                b_l[ni][0] = *(const uint32_t*)(p + PL_E);
                b_l[ni][1] = *(const uint32_t*)(p + PL_E + 8);
            }
#pragma unroll
            for (int mi = 0; mi < 4; mi++)
#pragma unroll
                for (int ni = 0; ni < 2; ni++) {
                    mma_f16(acc[mi][ni], a_h[mi], b_h[ni]);
                    mma_f16(acc[mi][ni], a_h[mi], b_l[ni]);
                    mma_f16(acc[mi][ni], a_l[mi], b_h[ni]);
                }
        }
        __syncthreads();
    }

#pragma unroll
    for (int mi = 0; mi < 4; mi++) {
        int r0 = bm + wm + mi * 16 + g, r1 = r0 + 8;
        float nv0 = npm[r0] * scale, nv1 = npm[r1] * scale;
#pragma unroll
        for (int ni = 0; ni < 2; ni++) {
            int c0 = bn + wn + ni * 8 + 2 * tg;
            float b0 = bias[c0], b1 = bias[c0 + 1];
            float v00 = (acc[mi][ni][0] + b0) * nv0, v01 = (acc[mi][ni][1] + b1) * nv0;
            float v10 = (acc[mi][ni][2] + b0) * nv1, v11 = (acc[mi][ni][3] + b1) * nv1;
            __half h00 = __float2half(v00), h01 = __float2half(v01);
            __half h10 = __float2half(v10), h11 = __float2half(v11);
            *(__half2*)&outH[(size_t)r0 * DD + c0] = __halves2half2(h00, h01);
            *(__half2*)&outH[(size_t)r1 * DD + c0] = __halves2half2(h10, h11);
            *(__half2*)&outL[(size_t)r0 * DD + c0] = __halves2half2(
                __float2half(v00 - __half2float(h00)), __float2half(v01 - __half2float(h01)));
            *(__half2*)&outL[(size_t)r1 * DD + c0] = __halves2half2(
                __float2half(v10 - __half2float(h10)), __float2half(v11 - __half2float(h11)));
        }
    }
}

// ===========================================================================
// single-term fp16 GEMM. outT != null: write transposed fp16 (V proj, vhT),
// else write fp32 (F proj).
// ===========================================================================
#define BUF1_B (2*PL_B)
#define GEMM1_SMEM (2*BUF1_B)

__global__ __launch_bounds__(512) void gemm_f16_1t(
    const __half* __restrict__ A, const __half* __restrict__ B,
    const float* __restrict__ bias, const float* __restrict__ npm, float scale,
    float* __restrict__ outF, __half* __restrict__ outT)
{
    extern __shared__ char sm[];
    const uint32_t smb = smem_u32(sm);
    const int tid = threadIdx.x, wid = tid >> 5, lane = tid & 31;
    const int g = lane >> 2, tg = lane & 3;
    const int bm = blockIdx.y * 128, bn = blockIdx.x * 128;
    const int wm = (wid & 1) * 64, wn = (wid >> 1) * 16;

    const __half* srcs[2] = { A + (size_t)bm * DD, B + (size_t)bn * DD };
    const int frow = tid >> 2, fc = tid & 3;

    float acc[4][2][4];
#pragma unroll
    for (int mi = 0; mi < 4; mi++)
#pragma unroll
        for (int ni = 0; ni < 2; ni++)
#pragma unroll
            for (int r = 0; r < 4; r++) acc[mi][ni][r] = 0.f;

#pragma unroll
    for (int i = 0; i < 2; i++)
        cp16(smb + i * PL_B + frow * 80 + fc * 16, srcs[i] + (size_t)frow * DD + fc * 8);
    CP_COMMIT;

    for (int kt = 0; kt < 32; kt++) {
        if (kt < 31) {
#pragma unroll
            for (int i = 0; i < 2; i++)
                cp16(smb + ((kt + 1) & 1) * BUF1_B + i * PL_B + frow * 80 + fc * 16,
                     srcs[i] + (size_t)frow * DD + (kt + 1) * 32 + fc * 8);
            CP_COMMIT;
            CP_WAIT1;
        } else {
            CP_WAIT0;
        }
        __syncthreads();

        const __half* buf = (const __half*)(sm + (kt & 1) * BUF1_B);
#pragma unroll
        for (int ks = 0; ks < 2; ks++) {
            uint32_t a_h[4][4], b_h[2][2];
#pragma unroll
            for (int mi = 0; mi < 4; mi++) {
                const __half* p = buf + (wm + mi * 16 + g) * 40 + ks * 16 + 2 * tg;
                a_h[mi][0] = *(const uint32_t*)(p);
                a_h[mi][1] = *(const uint32_t*)(p + 8 * 40);
                a_h[mi][2] = *(const uint32_t*)(p + 8);
                a_h[mi][3] = *(const uint32_t*)(p + 8 * 40 + 8);
            }
#pragma unroll
            for (int ni = 0; ni < 2; ni++) {
                const __half* p = buf + PL_E + (wn + ni * 8 + g) * 40 + ks * 16 + 2 * tg;
                b_h[ni][0] = *(const uint32_t*)(p);
                b_h[ni][1] = *(const uint32_t*)(p + 8);
            }
#pragma unroll
            for (int mi = 0; mi < 4; mi++)
#pragma unroll
                for (int ni = 0; ni < 2; ni++)
                    mma_f16(acc[mi][ni], a_h[mi], b_h[ni]);
        }
        __syncthreads();
    }

    if (!outT) {
#pragma unroll
        for (int mi = 0; mi < 4; mi++) {
            int r0 = bm + wm + mi * 16 + g, r1 = r0 + 8;
            float nv0 = npm[r0] * scale, nv1 = npm[r1] * scale;
#pragma unroll
            for (int ni = 0; ni < 2; ni++) {
                int c0 = bn + wn + ni * 8 + 2 * tg;
                float b0 = bias[c0], b1 = bias[c0 + 1];
                *(float2*)&outF[(size_t)r0 * DD + c0] =
                    make_float2((acc[mi][ni][0] + b0) * nv0, (acc[mi][ni][1] + b1) * nv0);
                *(float2*)&outF[(size_t)r1 * DD + c0] =
                    make_float2((acc[mi][ni][2] + b0) * nv1, (acc[mi][ni][3] + b1) * nv1);
            }
        }
    } else {
        // transpose staging: smT[col c][row r], stride 136 halfs
        __half* smT = (__half*)sm;
#pragma unroll
        for (int mi = 0; mi < 4; mi++) {
            int r = wm + mi * 16 + g;
            float nv0 = npm[bm + r], nv1 = npm[bm + r + 8];
#pragma unroll
            for (int ni = 0; ni < 2; ni++) {
                int c = wn + ni * 8 + 2 * tg;
                float b0 = bias[bn + c], b1 = bias[bn + c + 1];
                smT[c * 136 + r]           = __float2half((acc[mi][ni][0] + b0) * nv0 * scale);
                smT[(c + 1) * 136 + r]     = __float2half((acc[mi][ni][1] + b1) * nv0 * scale);
                smT[c * 136 + r + 8]       = __float2half((acc[mi][ni][2] + b0) * nv1 * scale);
                smT[(c + 1) * 136 + r + 8] = __float2half((acc[mi][ni][3] + b1) * nv1 * scale);
            }
        }
        __syncthreads();
        const int b = bm >> 10, token0 = bm & 1023;
#pragma unroll
        for (int p = 0; p < 4; p++) {
            int cr = (tid >> 4) + p * 32;      // 0..127
            int unit = tid & 15;               // 16 x 8 halfs
            int C = bn + cr;
            int h = C >> 6, d = C & 63;
            size_t dst = ((size_t)(b * 16 + h) * 64 + d) * 1024 + token0 + unit * 8;
            *(uint4*)&outT[dst] = *(const uint4*)&smT[cr * 136 + unit * 8];
        }
    }
}

// ===========================================================================
// Fused attention: block = (b,h) x 32 q-rows, 512 threads
// S = QK^T fp16-3term (K dbuf) -> mask+softmax (P->fp16 smem, attn->gmem)
// -> PV fp16 mma with pre-transposed V tiles (dbuf).
// S-phase smem: S 131584 | Qplanes 9216 | Kdbuf 2x36864  = 214528
// PV overlay:   Pf16 @QOFF stride 1036 (66304) | VT bufs @S+0 / @S+17408
// ===========================================================================
#define SSTR 1028
#define QOFF 131584
#define KOFF (QOFF + 9216)
#define KBUF 36864
#define KPLE 9216
#define ATT_SMEM (KOFF + 2*KBUF)     // 214528
#define POFF QOFF
#define PSTRB 2072                   // 1036 halfs
#define VTSTRB 272                   // 136 halfs
#define VTB0 0
#define VTB1 17408

__global__ __launch_bounds__(512) void attn_kernel(
    const __half* __restrict__ qhH, const __half* __restrict__ qhL,
    const __half* __restrict__ khH, const __half* __restrict__ khL,
    const __half* __restrict__ vhT, const int* __restrict__ mask,
    float* __restrict__ attn, __half* __restrict__ ctx)
{
    extern __shared__ char sm[];
    const uint32_t smb = smem_u32(sm);
    float* S = (float*)sm;
    const __half* Qh = (const __half*)(sm + QOFF);

    const int tid = threadIdx.x, wid = tid >> 5, lane = tid & 31;
    const int g = lane >> 2, tg = lane & 3;
    const int bh = blockIdx.x;
    const int b = bh >> 4, h = bh & 15;
    const int q0 = blockIdx.y * 32;
    const int wq = wid & 1;
    const int wk = wid >> 1;

    const __half* qHp = qhH + ((size_t)b * LL + q0) * DD + h * DK;
    const __half* qLp = qhL + ((size_t)b * LL + q0) * DD + h * DK;
    const __half* kHp = khH + (size_t)b * LL * DD + h * DK;
    const __half* kLp = khL + (size_t)b * LL * DD + h * DK;
    const __half* vTp = vhT + (size_t)bh * DK * LL;
    float* attnBase = attn + ((size_t)bh * LL + q0) * LL;

    // load Q planes + prefetch K chunk 0
    {
        int p = tid >> 8, rem = tid & 255, row = rem >> 3, c8 = rem & 7;
        cp16(smb + QOFF + p * 4608 + row * 144 + c8 * 16,
             (p ? qLp : qHp) + (size_t)row * DD + c8 * 8);
    }
#pragma unroll
    for (int j = 0; j < 4; j++) {
        int idx = tid + 512 * j;
        int p = idx >> 10, rem = idx & 1023, row = rem >> 3, c8 = rem & 7;
        cp16(smb + KOFF + p * 18432 + row * 144 + c8 * 16,
             (p ? kLp : kHp) + (size_t)row * DD + c8 * 8);
    }
    CP_COMMIT;

    // ---- S = Q K^T ----
    for (int kc = 0; kc < 8; kc++) {
        if (kc < 7) {
#pragma unroll
            for (int j = 0; j < 4; j++) {
                int idx = tid + 512 * j;
                int p = idx >> 10, rem = idx & 1023, row = rem >> 3, c8 = rem & 7;
                cp16(smb + KOFF + ((kc + 1) & 1) * KBUF + p * 18432 + row * 144 + c8 * 16,
                     (p ? kLp : kHp) + (size_t)((kc + 1) * 128 + row) * DD + c8 * 8);
            }
            CP_COMMIT;
            CP_WAIT1;
        } else {
            CP_WAIT0;
        }
        __syncthreads();

        const __half* Kb = (const __half*)(sm + KOFF + (kc & 1) * KBUF);
        float sacc[2][4];
#pragma unroll
        for (int ni = 0; ni < 2; ni++)
#pragma unroll
            for (int r = 0; r < 4; r++) sacc[ni][r] = 0.f;

#pragma unroll
        for (int ks = 0; ks < 4; ks++) {
            uint32_t a_h[4], a_l[4], b_h[2][2], b_l[2][2];
            const __half* qp = Qh + (wq * 16 + g) * 72 + ks * 16 + 2 * tg;
            a_h[0] = *(const uint32_t*)(qp);
            a_h[1] = *(const uint32_t*)(qp + 8 * 72);
            a_h[2] = *(const uint32_t*)(qp + 8);
            a_h[3] = *(const uint32_t*)(qp + 8 * 72 + 8);
            a_l[0] = *(const uint32_t*)(qp + 2304);
            a_l[1] = *(const uint32_t*)(qp + 2304 + 8 * 72);
            a_l[2] = *(const uint32_t*)(qp + 2304 + 8);
            a_l[3] = *(const uint32_t*)(qp + 2304 + 8 * 72 + 8);
#pragma unroll
            for (int ni = 0; ni < 2; ni++) {
                const __half* kp = Kb + (wk * 16 + ni * 8 + g) * 72 + ks * 16 + 2 * tg;
                b_h[ni][0] = *(const uint32_t*)(kp);
                b_h[ni][1] = *(const uint32_t*)(kp + 8);
                b_l[ni][0] = *(const uint32_t*)(kp + KPLE);
                b_l[ni][1] = *(const uint32_t*)(kp + KPLE + 8);
            }
#pragma unroll
            for (int ni = 0; ni < 2; ni++) {
                mma_f16(sacc[ni], a_h, b_h[ni]);
                mma_f16(sacc[ni], a_h, b_l[ni]);
                mma_f16(sacc[ni], a_l, b_h[ni]);
            }
        }
#pragma unroll
        for (int ni = 0; ni < 2; ni++) {
            int c = kc * 128 + wk * 16 + ni * 8 + 2 * tg;
            *(float2*)&S[(wq * 16 + g) * SSTR + c]     = make_float2(sacc[ni][0], sacc[ni][1]);
            *(float2*)&S[(wq * 16 + g + 8) * SSTR + c] = make_float2(sacc[ni][2], sacc[ni][3]);
        }
        __syncthreads();
    }

    // ---- mask + softmax; write attn (gmem) and P fp16 (smem @POFF) ----
#pragma unroll
    for (int rr = 0; rr < 2; rr++) {
        int r = wid * 2 + rr;
        float* Sr = S + r * SSTR;
        const int* mr = mask + ((size_t)b * LL + q0 + r) * LL;
        float m = -1e30f;
        for (int c = lane; c < 1024; c += 32) {
            float s = Sr[c];
            if (mr[c]) s = -1e30f;
            Sr[c] = s;
            m = fmaxf(m, s);
        }
#pragma unroll
        for (int o = 16; o; o >>= 1) m = fmaxf(m, __shfl_xor_sync(0xffffffffu, m, o));
        float sum = 0.f;
        for (int c = lane; c < 1024; c += 32) {
            float s = Sr[c];
            float e = (s <= -9e29f) ? 0.f : __expf(s - m);
            Sr[c] = e;
            sum += e;
        }
#pragma unroll
        for (int o = 16; o; o >>= 1) sum += __shfl_xor_sync(0xffffffffu, sum, o);
        float inv = 1.f / sum;
        float* dst = attnBase + (size_t)r * LL;
        __half* Pr = (__half*)(sm + POFF + r * PSTRB);
        for (int c = lane; c < 1024; c += 32) {
            float p = Sr[c] * inv;
            dst[c] = p;
            Pr[c] = __float2half(p);
        }
    }
    __syncthreads();   // P complete; S region now dead -> VT buffers

    // prefetch V^T chunk 0 into VT buf0 (S region)
#pragma unroll
    for (int j = 0; j < 2; j++) {
        int idx = tid + 512 * j;              // 0..1023
        int d = idx >> 4, tk = idx & 15;
        cp16(smb + VTB0 + d * VTSTRB + tk * 16, vTp + (size_t)d * LL + tk * 8);
    }
    CP_COMMIT;

    // ---- PV: fp16 mma, warp tile 16q x 8d ----
    float pacc[4] = {0.f, 0.f, 0.f, 0.f};
    for (int vc = 0; vc < 8; vc++) {
        if (vc < 7) {
#pragma unroll
            for (int j = 0; j < 2; j++) {
                int idx = tid + 512 * j;
                int d = idx >> 4, tk = idx & 15;
                cp16(smb + (((vc + 1) & 1) ? VTB1 : VTB0) + d * VTSTRB + tk * 16,
                     vTp + (size_t)d * LL + (vc + 1) * 128 + tk * 8);
            }
            CP_COMMIT;
            CP_WAIT1;
        } else {
            CP_WAIT0;
        }
        __syncthreads();

        const char* Vt = sm + ((vc & 1) ? VTB1 : VTB0);
        const char* Pb = sm + POFF + (wq * 16 + g) * PSTRB + vc * 256;
#pragma unroll
        for (int kk = 0; kk < 8; kk++) {
            uint32_t a[4], bfr[2];
            a[0] = *(const uint32_t*)(Pb + kk * 32 + tg * 4);
            a[1] = *(const uint32_t*)(Pb + 8 * PSTRB + kk * 32 + tg * 4);
            a[2] = *(const uint32_t*)(Pb + kk * 32 + tg * 4 + 16);
            a[3] = *(const uint32_t*)(Pb + 8 * PSTRB + kk * 32 + tg * 4 + 16);
            const char* vp = Vt + (wk * 8 + g) * VTSTRB + kk * 32 + tg * 4;
            bfr[0] = *(const uint32_t*)(vp);
            bfr[1] = *(const uint32_t*)(vp + 16);
            mma_f16(pacc, a, bfr);
        }
        __syncthreads();
    }

    {
        int c = h * DK + wk * 8 + 2 * tg;
        size_t r0 = (size_t)b * LL + q0 + wq * 16 + g;
        *(__half2*)&ctx[r0 * DD + c]       = __floats2half2_rn(pacc[0], pacc[1]);
        *(__half2*)&ctx[(r0 + 8) * DD + c] = __floats2half2_rn(pacc[2], pacc[3]);
    }
}

// ---------------------------------------------------------------------------
// LayerNorm(proj + residual) * g + b
// ---------------------------------------------------------------------------
__global__ __launch_bounds__(256) void ln_kernel(
    const float* __restrict__ proj, const float* __restrict__ resid,
    const float* __restrict__ gam, const float* __restrict__ bet,
    float* __restrict__ out)
{
    __shared__ float red[8];
    const int row = blockIdx.x;
    const int tid = threadIdx.x;
    const int c0 = tid * 4;
    const int lane = tid & 31, wid = tid >> 5;

    float4 pv = *(const float4*)(proj + (size_t)row * DD + c0);
    float4 rv = *(const float4*)(resid + (size_t)row * DD + c0);
    float x0 = pv.x + rv.x, x1 = pv.y + rv.y, x2 = pv.z + rv.z, x3 = pv.w + rv.w;

    float s = x0 + x1 + x2 + x3;
#pragma unroll
    for (int o = 16; o; o >>= 1) s += __shfl_xor_sync(0xffffffffu, s, o);
    if (lane == 0) red[wid] = s;
    __syncthreads();
    float tot = (lane < 8) ? red[lane] : 0.f;
#pragma unroll
    for (int o = 4; o; o >>= 1) tot += __shfl_xor_sync(0xffffffffu, tot, o);
    tot = __shfl_sync(0xffffffffu, tot, 0);
    float mean = tot * (1.f / 1024.f);

    float d0 = x0 - mean, d1 = x1 - mean, d2 = x2 - mean, d3 = x3 - mean;
    float sq = d0 * d0 + d1 * d1 + d2 * d2 + d3 * d3;
#pragma unroll
    for (int o = 16; o; o >>= 1) sq += __shfl_xor_sync(0xffffffffu, sq, o);
    __syncthreads();
    if (lane == 0) red[wid] = sq;
    __syncthreads();
    float tot2 = (lane < 8) ? red[lane] : 0.f;
#pragma unroll
    for (int o = 4; o; o >>= 1) tot2 += __shfl_xor_sync(0xffffffffu, tot2, o);
    tot2 = __shfl_sync(0xffffffffu, tot2, 0);
    float k = rsqrtf(tot2 * (1.f / 1024.f) + 1e-5f);

    float4 gv = *(const float4*)(gam + c0);
    float4 bv = *(const float4*)(bet + c0);
    float4 ov;
    ov.x = d0 * k * gv.x + bv.x;
    ov.y = d1 * k * gv.y + bv.y;
    ov.z = d2 * k * gv.z + bv.z;
    ov.w = d3 * k * gv.w + bv.w;
    *(float4*)&out[(size_t)row * DD + c0] = ov;
}

// ---------------------------------------------------------------------------
extern "C" void kernel_launch(void* const* d_in, const int* in_sizes, int n_in,
                              void* d_out, int out_size)
{
    const float* q    = (const float*)d_in[0];
    const float* k    = (const float*)d_in[1];
    const float* v    = (const float*)d_in[2];
    const int*   mask = (const int*)  d_in[3];
    const float* npm  = (const float*)d_in[4];
    const float* Wq   = (const float*)d_in[5];
    const float* bq   = (const float*)d_in[6];
    const float* Wk   = (const float*)d_in[7];
    const float* bk   = (const float*)d_in[8];
    const float* Wv   = (const float*)d_in[9];
    const float* bv   = (const float*)d_in[10];
    const float* Wf   = (const float*)d_in[11];
    const float* bf   = (const float*)d_in[12];
    const float* ln_g = (const float*)d_in[13];
    const float* ln_b = (const float*)d_in[14];

    float* out  = (float*)d_out;
    float* attn = out + (size_t)BB * LL * DD;

    __half *qhH, *qhL, *khH, *khL, *vhT, *ctx, *asH, *asL, *wsH, *wsL;
    float *proj;
    cudaGetSymbolAddress((void**)&qhH, g_qhH);
    cudaGetSymbolAddress((void**)&qhL, g_qhL);
    cudaGetSymbolAddress((void**)&khH, g_khH);
    cudaGetSymbolAddress((void**)&khL, g_khL);
    cudaGetSymbolAddress((void**)&vhT, g_vhT);
    cudaGetSymbolAddress((void**)&ctx, g_ctx);
    cudaGetSymbolAddress((void**)&proj, g_proj);
    cudaGetSymbolAddress((void**)&asH, g_asH);
    cudaGetSymbolAddress((void**)&asL, g_asL);
    cudaGetSymbolAddress((void**)&wsH, g_wsH);
    cudaGetSymbolAddress((void**)&wsL, g_wsL);

    cudaFuncSetAttribute(gemm_f16_3t, cudaFuncAttributeMaxDynamicSharedMemorySize, GEMM_SMEM);
    cudaFuncSetAttribute(gemm_f16_1t, cudaFuncAttributeMaxDynamicSharedMemorySize, GEMM1_SMEM);
    cudaFuncSetAttribute(attn_kernel, cudaFuncAttributeMaxDynamicSharedMemorySize, ATT_SMEM);

    const int nA4 = ROWS_TOT * DD / 4;
    const int nW4 = DD * DD / 4;
    dim3 gG(DD / 128, ROWS_TOT / 128);   // (8, 64)

    // Q projection (scale 1/8 folded), fp16 3-term -> fp16 planes
    split_f16<<<(nA4 + 255) / 256, 256>>>(q, asH, asL, nA4);
    split_f16<<<(nW4 + 255) / 256, 256>>>(Wq, wsH, wsL, nW4);
    gemm_f16_3t<<<gG, 512, GEMM_SMEM>>>(asH, asL, wsH, wsL, bq, npm, 0.125f, qhH, qhL);
    // K projection
    split_f16<<<(nA4 + 255) / 256, 256>>>(k, asH, asL, nA4);
    split_f16<<<(nW4 + 255) / 256, 256>>>(Wk, wsH, wsL, nW4);
    gemm_f16_3t<<<gG, 512, GEMM_SMEM>>>(asH, asL, wsH, wsL, bk, npm, 1.0f, khH, khL);
    // V projection -> transposed fp16 vhT
    conv_f16<<<(nA4 + 255) / 256, 256>>>(v, asH, nA4);
    conv_f16<<<(nW4 + 255) / 256, 256>>>(Wv, wsH, nW4);
    gemm_f16_1t<<<gG, 512, GEMM1_SMEM>>>(asH, wsH, bv, npm, 1.0f, nullptr, vhT);

    // Fused attention (ctx out as fp16)
    attn_kernel<<<dim3(BB * HH, LL / 32), 512, ATT_SMEM>>>(
        qhH, qhL, khH, khL, vhT, mask, attn, ctx);

    // Output projection (ctx fp16 direct), then LN
    conv_f16<<<(nW4 + 255) / 256, 256>>>(Wf, wsH, nW4);
    gemm_f16_1t<<<gG, 512, GEMM1_SMEM>>>(ctx, wsH, bf, npm, 1.0f, proj, nullptr);

    ln_kernel<<<ROWS_TOT, 256>>>(proj, q, ln_g, ln_b, out);
}

// round 10
// speedup vs baseline: 1.8858x; 1.3402x over previous
#include <cuda_runtime.h>
#include <cuda_fp16.h>
#include <math.h>
#include <cstdint>

#define BB 8
#define LL 1024
#define DD 1024
#define HH 16
#define DK 64
#define ROWS_TOT (BB*LL)          // 8192

// Scratch (device globals)
__device__ __half g_qh [(size_t)ROWS_TOT * DD];   // fp16 q heads (scaled 1/8)
__device__ __half g_kh [(size_t)ROWS_TOT * DD];   // fp16 k heads
__device__ __half g_vhT[(size_t)ROWS_TOT * DD];   // [b][h][d][token] fp16
__device__ __half g_ctx[(size_t)ROWS_TOT * DD];   // fp16
__device__ float  g_proj[(size_t)ROWS_TOT * DD];
__device__ __half g_as [(size_t)ROWS_TOT * DD];
__device__ __half g_ws [(size_t)DD * DD];

// ---------------------------------------------------------------------------
// helpers
// ---------------------------------------------------------------------------
__device__ __forceinline__ uint32_t smem_u32(const void* p) {
    uint32_t a;
    asm("{ .reg .u64 t; cvta.to.shared.u64 t, %1; cvt.u32.u64 %0, t; }" : "=r"(a) : "l"(p));
    return a;
}
__device__ __forceinline__ void cp16(uint32_t dst, const void* src) {
    asm volatile("cp.async.cg.shared.global [%0], [%1], 16;" :: "r"(dst), "l"(src));
}
#define CP_COMMIT asm volatile("cp.async.commit_group;" ::: "memory")
#define CP_WAIT1  asm volatile("cp.async.wait_group 1;" ::: "memory")
#define CP_WAIT0  asm volatile("cp.async.wait_group 0;" ::: "memory")

__device__ __forceinline__ void mma_f16(float* c, const uint32_t* a, const uint32_t* b) {
    asm volatile(
        "mma.sync.aligned.m16n8k16.row.col.f32.f16.f16.f32 "
        "{%0,%1,%2,%3},{%4,%5,%6,%7},{%8,%9},{%0,%1,%2,%3};"
        : "+f"(c[0]), "+f"(c[1]), "+f"(c[2]), "+f"(c[3])
        : "r"(a[0]), "r"(a[1]), "r"(a[2]), "r"(a[3]), "r"(b[0]), "r"(b[1]));
}

// f32 -> fp16 convert
__global__ __launch_bounds__(256) void conv_f16(
    const float* __restrict__ x, __half* __restrict__ hi, int n4)
{
    int i = blockIdx.x * blockDim.x + threadIdx.x;
    if (i >= n4) return;
    float4 v = ((const float4*)x)[i];
    ((__half2*)hi)[i * 2]     = __floats2half2_rn(v.x, v.y);
    ((__half2*)hi)[i * 2 + 1] = __floats2half2_rn(v.z, v.w);
}

// ===========================================================================
// single-term fp16 GEMM. Output modes:
//   outT: transposed fp16 (V proj -> vhT)   | outH: planar fp16 (Q/K proj)
//   outF: fp32 (F proj)
// 128x128 tile, BK=32, 512 threads
// ===========================================================================
#define PL_E 5120
#define PL_B (PL_E*2)
#define BUF1_B (2*PL_B)
#define GEMM1_SMEM (2*BUF1_B)

__global__ __launch_bounds__(512) void gemm_f16_1t(
    const __half* __restrict__ A, const __half* __restrict__ B,
    const float* __restrict__ bias, const float* __restrict__ npm, float scale,
    float* __restrict__ outF, __half* __restrict__ outH, __half* __restrict__ outT)
{
    extern __shared__ char sm[];
    const uint32_t smb = smem_u32(sm);
    const int tid = threadIdx.x, wid = tid >> 5, lane = tid & 31;
    const int g = lane >> 2, tg = lane & 3;
    const int bm = blockIdx.y * 128, bn = blockIdx.x * 128;
    const int wm = (wid & 1) * 64, wn = (wid >> 1) * 16;

    const __half* srcs[2] = { A + (size_t)bm * DD, B + (size_t)bn * DD };
    const int frow = tid >> 2, fc = tid & 3;

    float acc[4][2][4];
#pragma unroll
    for (int mi = 0; mi < 4; mi++)
#pragma unroll
        for (int ni = 0; ni < 2; ni++)
#pragma unroll
            for (int r = 0; r < 4; r++) acc[mi][ni][r] = 0.f;

#pragma unroll
    for (int i = 0; i < 2; i++)
        cp16(smb + i * PL_B + frow * 80 + fc * 16, srcs[i] + (size_t)frow * DD + fc * 8);
    CP_COMMIT;

    for (int kt = 0; kt < 32; kt++) {
        if (kt < 31) {
#pragma unroll
            for (int i = 0; i < 2; i++)
                cp16(smb + ((kt + 1) & 1) * BUF1_B + i * PL_B + frow * 80 + fc * 16,
                     srcs[i] + (size_t)frow * DD + (kt + 1) * 32 + fc * 8);
            CP_COMMIT;
            CP_WAIT1;
        } else {
            CP_WAIT0;
        }
        __syncthreads();

        const __half* buf = (const __half*)(sm + (kt & 1) * BUF1_B);
#pragma unroll
        for (int ks = 0; ks < 2; ks++) {
            uint32_t a_h[4][4], b_h[2][2];
#pragma unroll
            for (int mi = 0; mi < 4; mi++) {
                const __half* p = buf + (wm + mi * 16 + g) * 40 + ks * 16 + 2 * tg;
                a_h[mi][0] = *(const uint32_t*)(p);
                a_h[mi][1] = *(const uint32_t*)(p + 8 * 40);
                a_h[mi][2] = *(const uint32_t*)(p + 8);
                a_h[mi][3] = *(const uint32_t*)(p + 8 * 40 + 8);
            }
#pragma unroll
            for (int ni = 0; ni < 2; ni++) {
                const __half* p = buf + PL_E + (wn + ni * 8 + g) * 40 + ks * 16 + 2 * tg;
                b_h[ni][0] = *(const uint32_t*)(p);
                b_h[ni][1] = *(const uint32_t*)(p + 8);
            }
#pragma unroll
            for (int mi = 0; mi < 4; mi++)
#pragma unroll
                for (int ni = 0; ni < 2; ni++)
                    mma_f16(acc[mi][ni], a_h[mi], b_h[ni]);
        }
        __syncthreads();
    }

    if (outT) {
        // transpose staging: smT[col c][row r], stride 136 halfs
        __half* smT = (__half*)sm;
#pragma unroll
        for (int mi = 0; mi < 4; mi++) {
            int r = wm + mi * 16 + g;
            float nv0 = npm[bm + r] * scale, nv1 = npm[bm + r + 8] * scale;
#pragma unroll
            for (int ni = 0; ni < 2; ni++) {
                int c = wn + ni * 8 + 2 * tg;
                float b0 = bias[bn + c], b1 = bias[bn + c + 1];
                smT[c * 136 + r]           = __float2half((acc[mi][ni][0] + b0) * nv0);
                smT[(c + 1) * 136 + r]     = __float2half((acc[mi][ni][1] + b1) * nv0);
                smT[c * 136 + r + 8]       = __float2half((acc[mi][ni][2] + b0) * nv1);
                smT[(c + 1) * 136 + r + 8] = __float2half((acc[mi][ni][3] + b1) * nv1);
            }
        }
        __syncthreads();
        const int b = bm >> 10, token0 = bm & 1023;
#pragma unroll
        for (int p = 0; p < 4; p++) {
            int cr = (tid >> 4) + p * 32;
            int unit = tid & 15;
            int C = bn + cr;
            int h = C >> 6, d = C & 63;
            size_t dst = ((size_t)(b * 16 + h) * 64 + d) * 1024 + token0 + unit * 8;
            *(uint4*)&outT[dst] = *(const uint4*)&smT[cr * 136 + unit * 8];
        }
    } else if (outH) {
#pragma unroll
        for (int mi = 0; mi < 4; mi++) {
            int r0 = bm + wm + mi * 16 + g, r1 = r0 + 8;
            float nv0 = npm[r0] * scale, nv1 = npm[r1] * scale;
#pragma unroll
            for (int ni = 0; ni < 2; ni++) {
                int c0 = bn + wn + ni * 8 + 2 * tg;
                float b0 = bias[c0], b1 = bias[c0 + 1];
                *(__half2*)&outH[(size_t)r0 * DD + c0] =
                    __floats2half2_rn((acc[mi][ni][0] + b0) * nv0, (acc[mi][ni][1] + b1) * nv0);
                *(__half2*)&outH[(size_t)r1 * DD + c0] =
                    __floats2half2_rn((acc[mi][ni][2] + b0) * nv1, (acc[mi][ni][3] + b1) * nv1);
            }
        }
    } else {
#pragma unroll
        for (int mi = 0; mi < 4; mi++) {
            int r0 = bm + wm + mi * 16 + g, r1 = r0 + 8;
            float nv0 = npm[r0] * scale, nv1 = npm[r1] * scale;
#pragma unroll
            for (int ni = 0; ni < 2; ni++) {
                int c0 = bn + wn + ni * 8 + 2 * tg;
                float b0 = bias[c0], b1 = bias[c0 + 1];
                *(float2*)&outF[(size_t)r0 * DD + c0] =
                    make_float2((acc[mi][ni][0] + b0) * nv0, (acc[mi][ni][1] + b1) * nv0);
                *(float2*)&outF[(size_t)r1 * DD + c0] =
                    make_float2((acc[mi][ni][2] + b0) * nv1, (acc[mi][ni][3] + b1) * nv1);
            }
        }
    }
}

// ===========================================================================
// Fused attention: block = (b,h) x 32 q-rows, 512 threads
// S = QK^T single fp16 (K dbuf) -> mask+softmax (P->fp16 smem, attn->gmem)
// -> PV fp16 mma with pre-transposed V tiles (dbuf).
// smem: S 131584 | Q 4608 | K dbuf 2x18432 ; P overlay @QOFF needs 66304
// ===========================================================================
#define SSTR 1028
#define QOFF 131584
#define KOFF (QOFF + 4608)
#define KBUF 18432
#define ATT_SMEM (QOFF + 66304)      // 197888 (covers Q+K and P overlay)
#define POFF QOFF
#define PSTRB 2072                   // 1036 halfs
#define VTSTRB 272                   // 136 halfs
#define VTB0 0
#define VTB1 17408

__global__ __launch_bounds__(512) void attn_kernel(
    const __half* __restrict__ qh, const __half* __restrict__ kh,
    const __half* __restrict__ vhT, const int* __restrict__ mask,
    float* __restrict__ attn, __half* __restrict__ ctx)
{
    extern __shared__ char sm[];
    const uint32_t smb = smem_u32(sm);
    float* S = (float*)sm;
    const __half* Qs = (const __half*)(sm + QOFF);

    const int tid = threadIdx.x, wid = tid >> 5, lane = tid & 31;
    const int g = lane >> 2, tg = lane & 3;
    const int bh = blockIdx.x;
    const int b = bh >> 4, h = bh & 15;
    const int q0 = blockIdx.y * 32;
    const int wq = wid & 1;
    const int wk = wid >> 1;

    const __half* qp_g = qh + ((size_t)b * LL + q0) * DD + h * DK;
    const __half* kp_g = kh + (size_t)b * LL * DD + h * DK;
    const __half* vTp = vhT + (size_t)bh * DK * LL;
    float* attnBase = attn + ((size_t)bh * LL + q0) * LL;

    // load Q (32x64 fp16) + prefetch K chunk 0
    if (tid < 256) {
        int row = tid >> 3, c8 = tid & 7;
        cp16(smb + QOFF + row * 144 + c8 * 16, qp_g + (size_t)row * DD + c8 * 8);
    }
#pragma unroll
    for (int j = 0; j < 2; j++) {
        int idx = tid + 512 * j;          // 0..1023
        int row = idx >> 3, c8 = idx & 7;
        cp16(smb + KOFF + row * 144 + c8 * 16, kp_g + (size_t)row * DD + c8 * 8);
    }
    CP_COMMIT;

    // ---- S = Q K^T over 8 double-buffered chunks of 128 k-rows ----
    for (int kc = 0; kc < 8; kc++) {
        if (kc < 7) {
#pragma unroll
            for (int j = 0; j < 2; j++) {
                int idx = tid + 512 * j;
                int row = idx >> 3, c8 = idx & 7;
                cp16(smb + KOFF + ((kc + 1) & 1) * KBUF + row * 144 + c8 * 16,
                     kp_g + (size_t)((kc + 1) * 128 + row) * DD + c8 * 8);
            }
            CP_COMMIT;
            CP_WAIT1;
        } else {
            CP_WAIT0;
        }
        __syncthreads();

        const __half* Kb = (const __half*)(sm + KOFF + (kc & 1) * KBUF);
        float sacc[2][4];
#pragma unroll
        for (int ni = 0; ni < 2; ni++)
#pragma unroll
            for (int r = 0; r < 4; r++) sacc[ni][r] = 0.f;

#pragma unroll
        for (int ks = 0; ks < 4; ks++) {
            uint32_t a_h[4], b_h[2][2];
            const __half* qp = Qs + (wq * 16 + g) * 72 + ks * 16 + 2 * tg;
            a_h[0] = *(const uint32_t*)(qp);
            a_h[1] = *(const uint32_t*)(qp + 8 * 72);
            a_h[2] = *(const uint32_t*)(qp + 8);
            a_h[3] = *(const uint32_t*)(qp + 8 * 72 + 8);
#pragma unroll
            for (int ni = 0; ni < 2; ni++) {
                const __half* kp = Kb + (wk * 16 + ni * 8 + g) * 72 + ks * 16 + 2 * tg;
                b_h[ni][0] = *(const uint32_t*)(kp);
                b_h[ni][1] = *(const uint32_t*)(kp + 8);
            }
            mma_f16(sacc[0], a_h, b_h[0]);
            mma_f16(sacc[1], a_h, b_h[1]);
        }
#pragma unroll
        for (int ni = 0; ni < 2; ni++) {
            int c = kc * 128 + wk * 16 + ni * 8 + 2 * tg;
            *(float2*)&S[(wq * 16 + g) * SSTR + c]     = make_float2(sacc[ni][0], sacc[ni][1]);
            *(float2*)&S[(wq * 16 + g + 8) * SSTR + c] = make_float2(sacc[ni][2], sacc[ni][3]);
        }
        __syncthreads();
    }

    // ---- mask + softmax; write attn (gmem) and P fp16 (smem @POFF) ----
#pragma unroll
    for (int rr = 0; rr < 2; rr++) {
        int r = wid * 2 + rr;
        float* Sr = S + r * SSTR;
        const int* mr = mask + ((size_t)b * LL + q0 + r) * LL;
        float m = -1e30f;
        for (int c = lane; c < 1024; c += 32) {
            float s = Sr[c];
            if (mr[c]) s = -1e30f;
            Sr[c] = s;
            m = fmaxf(m, s);
        }
#pragma unroll
        for (int o = 16; o; o >>= 1) m = fmaxf(m, __shfl_xor_sync(0xffffffffu, m, o));
        float sum = 0.f;
        for (int c = lane; c < 1024; c += 32) {
            float s = Sr[c];
            float e = (s <= -9e29f) ? 0.f : __expf(s - m);
            Sr[c] = e;
            sum += e;
        }
#pragma unroll
        for (int o = 16; o; o >>= 1) sum += __shfl_xor_sync(0xffffffffu, sum, o);
        float inv = 1.f / sum;
        float* dst = attnBase + (size_t)r * LL;
        __half* Pr = (__half*)(sm + POFF + r * PSTRB);
        for (int c = lane; c < 1024; c += 32) {
            float p = Sr[c] * inv;
            dst[c] = p;
            Pr[c] = __float2half(p);
        }
    }
    __syncthreads();   // P complete; S region now dead -> VT buffers

    // prefetch V^T chunk 0 into VT buf0 (S region)
#pragma unroll
    for (int j = 0; j < 2; j++) {
        int idx = tid + 512 * j;              // 0..1023
        int d = idx >> 4, tk = idx & 15;
        cp16(smb + VTB0 + d * VTSTRB + tk * 16, vTp + (size_t)d * LL + tk * 8);
    }
    CP_COMMIT;

    // ---- PV: fp16 mma, warp tile 16q x 8d ----
    float pacc[4] = {0.f, 0.f, 0.f, 0.f};
    for (int vc = 0; vc < 8; vc++) {
        if (vc < 7) {
#pragma unroll
            for (int j = 0; j < 2; j++) {
                int idx = tid + 512 * j;
                int d = idx >> 4, tk = idx & 15;
                cp16(smb + (((vc + 1) & 1) ? VTB1 : VTB0) + d * VTSTRB + tk * 16,
                     vTp + (size_t)d * LL + (vc + 1) * 128 + tk * 8);
            }
            CP_COMMIT;
            CP_WAIT1;
        } else {
            CP_WAIT0;
        }
        __syncthreads();

        const char* Vt = sm + ((vc & 1) ? VTB1 : VTB0);
        const char* Pb = sm + POFF + (wq * 16 + g) * PSTRB + vc * 256;
#pragma unroll
        for (int kk = 0; kk < 8; kk++) {
            uint32_t a[4], bfr[2];
            a[0] = *(const uint32_t*)(Pb + kk * 32 + tg * 4);
            a[1] = *(const uint32_t*)(Pb + 8 * PSTRB + kk * 32 + tg * 4);
            a[2] = *(const uint32_t*)(Pb + kk * 32 + tg * 4 + 16);
            a[3] = *(const uint32_t*)(Pb + 8 * PSTRB + kk * 32 + tg * 4 + 16);
            const char* vp = Vt + (wk * 8 + g) * VTSTRB + kk * 32 + tg * 4;
            bfr[0] = *(const uint32_t*)(vp);
            bfr[1] = *(const uint32_t*)(vp + 16);
            mma_f16(pacc, a, bfr);
        }
        __syncthreads();
    }

    {
        int c = h * DK + wk * 8 + 2 * tg;
        size_t r0 = (size_t)b * LL + q0 + wq * 16 + g;
        *(__half2*)&ctx[r0 * DD + c]       = __floats2half2_rn(pacc[0], pacc[1]);
        *(__half2*)&ctx[(r0 + 8) * DD + c] = __floats2half2_rn(pacc[2], pacc[3]);
    }
}

// ---------------------------------------------------------------------------
// LayerNorm(proj + residual) * g + b
// ---------------------------------------------------------------------------
__global__ __launch_bounds__(256) void ln_kernel(
    const float* __restrict__ proj, const float* __restrict__ resid,
    const float* __restrict__ gam, const float* __restrict__ bet,
    float* __restrict__ out)
{
    __shared__ float red[8];
    const int row = blockIdx.x;
    const int tid = threadIdx.x;
    const int c0 = tid * 4;
    const int lane = tid & 31, wid = tid >> 5;

    float4 pv = *(const float4*)(proj + (size_t)row * DD + c0);
    float4 rv = *(const float4*)(resid + (size_t)row * DD + c0);
    float x0 = pv.x + rv.x, x1 = pv.y + rv.y, x2 = pv.z + rv.z, x3 = pv.w + rv.w;

    float s = x0 + x1 + x2 + x3;
#pragma unroll
    for (int o = 16; o; o >>= 1) s += __shfl_xor_sync(0xffffffffu, s, o);
    if (lane == 0) red[wid] = s;
    __syncthreads();
    float tot = (lane < 8) ? red[lane] : 0.f;
#pragma unroll
    for (int o = 4; o; o >>= 1) tot += __shfl_xor_sync(0xffffffffu, tot, o);
    tot = __shfl_sync(0xffffffffu, tot, 0);
    float mean = tot * (1.f / 1024.f);

    float d0 = x0 - mean, d1 = x1 - mean, d2 = x2 - mean, d3 = x3 - mean;
    float sq = d0 * d0 + d1 * d1 + d2 * d2 + d3 * d3;
#pragma unroll
    for (int o = 16; o; o >>= 1) sq += __shfl_xor_sync(0xffffffffu, sq, o);
    __syncthreads();
    if (lane == 0) red[wid] = sq;
    __syncthreads();
    float tot2 = (lane < 8) ? red[lane] : 0.f;
#pragma unroll
    for (int o = 4; o; o >>= 1) tot2 += __shfl_xor_sync(0xffffffffu, tot2, o);
    tot2 = __shfl_sync(0xffffffffu, tot2, 0);
    float k = rsqrtf(tot2 * (1.f / 1024.f) + 1e-5f);

    float4 gv = *(const float4*)(gam + c0);
    float4 bv = *(const float4*)(bet + c0);
    float4 ov;
    ov.x = d0 * k * gv.x + bv.x;
    ov.y = d1 * k * gv.y + bv.y;
    ov.z = d2 * k * gv.z + bv.z;
    ov.w = d3 * k * gv.w + bv.w;
    *(float4*)&out[(size_t)row * DD + c0] = ov;
}

// ---------------------------------------------------------------------------
extern "C" void kernel_launch(void* const* d_in, const int* in_sizes, int n_in,
                              void* d_out, int out_size)
{
    const float* q    = (const float*)d_in[0];
    const float* k    = (const float*)d_in[1];
    const float* v    = (const float*)d_in[2];
    const int*   mask = (const int*)  d_in[3];
    const float* npm  = (const float*)d_in[4];
    const float* Wq   = (const float*)d_in[5];
    const float* bq   = (const float*)d_in[6];
    const float* Wk   = (const float*)d_in[7];
    const float* bk   = (const float*)d_in[8];
    const float* Wv   = (const float*)d_in[9];
    const float* bv   = (const float*)d_in[10];
    const float* Wf   = (const float*)d_in[11];
    const float* bf   = (const float*)d_in[12];
    const float* ln_g = (const float*)d_in[13];
    const float* ln_b = (const float*)d_in[14];

    float* out  = (float*)d_out;
    float* attn = out + (size_t)BB * LL * DD;

    __half *qh, *kh, *vhT, *ctx, *as, *ws;
    float *proj;
    cudaGetSymbolAddress((void**)&qh,  g_qh);
    cudaGetSymbolAddress((void**)&kh,  g_kh);
    cudaGetSymbolAddress((void**)&vhT, g_vhT);
    cudaGetSymbolAddress((void**)&ctx, g_ctx);
    cudaGetSymbolAddress((void**)&proj, g_proj);
    cudaGetSymbolAddress((void**)&as,  g_as);
    cudaGetSymbolAddress((void**)&ws,  g_ws);

    cudaFuncSetAttribute(gemm_f16_1t, cudaFuncAttributeMaxDynamicSharedMemorySize, GEMM1_SMEM);
    cudaFuncSetAttribute(attn_kernel, cudaFuncAttributeMaxDynamicSharedMemorySize, ATT_SMEM);

    const int nA4 = ROWS_TOT * DD / 4;
    const int nW4 = DD * DD / 4;
    dim3 gG(DD / 128, ROWS_TOT / 128);   // (8, 64)

    // Q projection (scale 1/8 folded) -> fp16
    conv_f16<<<(nA4 + 255) / 256, 256>>>(q, as, nA4);
    conv_f16<<<(nW4 + 255) / 256, 256>>>(Wq, ws, nW4);
    gemm_f16_1t<<<gG, 512, GEMM1_SMEM>>>(as, ws, bq, npm, 0.125f, nullptr, qh, nullptr);
    // K projection -> fp16
    conv_f16<<<(nA4 + 255) / 256, 256>>>(k, as, nA4);
    conv_f16<<<(nW4 + 255) / 256, 256>>>(Wk, ws, nW4);
    gemm_f16_1t<<<gG, 512, GEMM1_SMEM>>>(as, ws, bk, npm, 1.0f, nullptr, kh, nullptr);
    // V projection -> transposed fp16 vhT
    conv_f16<<<(nA4 + 255) / 256, 256>>>(v, as, nA4);
    conv_f16<<<(nW4 + 255) / 256, 256>>>(Wv, ws, nW4);
    gemm_f16_1t<<<gG, 512, GEMM1_SMEM>>>(as, ws, bv, npm, 1.0f, nullptr, nullptr, vhT);

    // Fused attention (ctx out as fp16)
    attn_kernel<<<dim3(BB * HH, LL / 32), 512, ATT_SMEM>>>(
        qh, kh, vhT, mask, attn, ctx);

    // Output projection (ctx fp16 direct) -> fp32, then LN
    conv_f16<<<(nW4 + 255) / 256, 256>>>(Wf, ws, nW4);
    gemm_f16_1t<<<gG, 512, GEMM1_SMEM>>>(ctx, ws, bf, npm, 1.0f, proj, nullptr, nullptr);

    ln_kernel<<<ROWS_TOT, 256>>>(proj, q, ln_g, ln_b, out);
}

// round 11
// speedup vs baseline: 2.0480x; 1.0860x over previous
#include <cuda_runtime.h>
#include <cuda_fp16.h>
#include <math.h>
#include <cstdint>

#define BB 8
#define LL 1024
#define DD 1024
#define HH 16
#define DK 64
#define ROWS_TOT (BB*LL)          // 8192

// Scratch (device globals)
__device__ __half g_qh [(size_t)ROWS_TOT * DD];   // fp16 q heads (scaled 1/8)
__device__ __half g_kh [(size_t)ROWS_TOT * DD];   // fp16 k heads
__device__ __half g_vhT[(size_t)ROWS_TOT * DD];   // [b][h][d][token] fp16
__device__ __half g_ctx[(size_t)ROWS_TOT * DD];   // fp16
__device__ float  g_proj[(size_t)ROWS_TOT * DD];
__device__ __half g_as [(size_t)ROWS_TOT * DD];
__device__ __half g_ws [(size_t)DD * DD];

// ---------------------------------------------------------------------------
// helpers
// ---------------------------------------------------------------------------
__device__ __forceinline__ uint32_t smem_u32(const void* p) {
    uint32_t a;
    asm("{ .reg .u64 t; cvta.to.shared.u64 t, %1; cvt.u32.u64 %0, t; }" : "=r"(a) : "l"(p));
    return a;
}
__device__ __forceinline__ void cp16(uint32_t dst, const void* src) {
    asm volatile("cp.async.cg.shared.global [%0], [%1], 16;" :: "r"(dst), "l"(src));
}
#define CP_COMMIT asm volatile("cp.async.commit_group;" ::: "memory")
#define CP_WAIT2  asm volatile("cp.async.wait_group 2;" ::: "memory")
#define CP_WAIT1  asm volatile("cp.async.wait_group 1;" ::: "memory")
#define CP_WAIT0  asm volatile("cp.async.wait_group 0;" ::: "memory")

__device__ __forceinline__ void mma_f16(float* c, const uint32_t* a, const uint32_t* b) {
    asm volatile(
        "mma.sync.aligned.m16n8k16.row.col.f32.f16.f16.f32 "
        "{%0,%1,%2,%3},{%4,%5,%6,%7},{%8,%9},{%0,%1,%2,%3};"
        : "+f"(c[0]), "+f"(c[1]), "+f"(c[2]), "+f"(c[3])
        : "r"(a[0]), "r"(a[1]), "r"(a[2]), "r"(a[3]), "r"(b[0]), "r"(b[1]));
}
__device__ __forceinline__ void ldsm4(uint32_t& r0, uint32_t& r1, uint32_t& r2,
                                      uint32_t& r3, uint32_t addr) {
    asm volatile("ldmatrix.sync.aligned.m8n8.x4.shared.b16 {%0,%1,%2,%3}, [%4];"
                 : "=r"(r0), "=r"(r1), "=r"(r2), "=r"(r3) : "r"(addr));
}
__device__ __forceinline__ void ldsm2(uint32_t& r0, uint32_t& r1, uint32_t addr) {
    asm volatile("ldmatrix.sync.aligned.m8n8.x2.shared.b16 {%0,%1}, [%2];"
                 : "=r"(r0), "=r"(r1) : "r"(addr));
}

// f32 -> fp16 convert
__global__ __launch_bounds__(256) void conv_f16(
    const float* __restrict__ x, __half* __restrict__ hi, int n4)
{
    int i = blockIdx.x * blockDim.x + threadIdx.x;
    if (i >= n4) return;
    float4 v = ((const float4*)x)[i];
    ((__half2*)hi)[i * 2]     = __floats2half2_rn(v.x, v.y);
    ((__half2*)hi)[i * 2 + 1] = __floats2half2_rn(v.z, v.w);
}

// ===========================================================================
// single-term fp16 GEMM (ldmatrix fragments). Output modes:
//   outT: transposed fp16 (V proj -> vhT) | outH: planar fp16 (Q/K) | outF: fp32
// 128x128 tile, BK=32, 512 threads
// ===========================================================================
#define PL_E 5120
#define PL_B (PL_E*2)
#define BUF1_B (2*PL_B)
#define GEMM1_SMEM (2*BUF1_B)

__global__ __launch_bounds__(512) void gemm_f16_1t(
    const __half* __restrict__ A, const __half* __restrict__ B,
    const float* __restrict__ bias, const float* __restrict__ npm, float scale,
    float* __restrict__ outF, __half* __restrict__ outH, __half* __restrict__ outT)
{
    extern __shared__ char sm[];
    const uint32_t smb = smem_u32(sm);
    const int tid = threadIdx.x, wid = tid >> 5, lane = tid & 31;
    const int g = lane >> 2, tg = lane & 3;
    const int bm = blockIdx.y * 128, bn = blockIdx.x * 128;
    const int wm = (wid & 1) * 64, wn = (wid >> 1) * 16;
    const int lrow = lane & 15, lkh = (lane >> 4) * 16;   // ldsm row / k-half byte

    const __half* srcs[2] = { A + (size_t)bm * DD, B + (size_t)bn * DD };
    const int frow = tid >> 2, fc = tid & 3;

    float acc[4][2][4];
#pragma unroll
    for (int mi = 0; mi < 4; mi++)
#pragma unroll
        for (int ni = 0; ni < 2; ni++)
#pragma unroll
            for (int r = 0; r < 4; r++) acc[mi][ni][r] = 0.f;

#pragma unroll
    for (int i = 0; i < 2; i++)
        cp16(smb + i * PL_B + frow * 80 + fc * 16, srcs[i] + (size_t)frow * DD + fc * 8);
    CP_COMMIT;

    for (int kt = 0; kt < 32; kt++) {
        if (kt < 31) {
#pragma unroll
            for (int i = 0; i < 2; i++)
                cp16(smb + ((kt + 1) & 1) * BUF1_B + i * PL_B + frow * 80 + fc * 16,
                     srcs[i] + (size_t)frow * DD + (kt + 1) * 32 + fc * 8);
            CP_COMMIT;
            CP_WAIT1;
        } else {
            CP_WAIT0;
        }
        __syncthreads();

        const uint32_t bufb = smb + (kt & 1) * BUF1_B;
#pragma unroll
        for (int ks = 0; ks < 2; ks++) {
            uint32_t a_h[4][4], b4[4], b_h[2][2];
#pragma unroll
            for (int mi = 0; mi < 4; mi++)
                ldsm4(a_h[mi][0], a_h[mi][1], a_h[mi][2], a_h[mi][3],
                      bufb + (wm + mi * 16 + lrow) * 80 + ks * 32 + lkh);
            ldsm4(b4[0], b4[1], b4[2], b4[3],
                  bufb + PL_B + (wn + lrow) * 80 + ks * 32 + lkh);
            b_h[0][0] = b4[0]; b_h[0][1] = b4[2];
            b_h[1][0] = b4[1]; b_h[1][1] = b4[3];
#pragma unroll
            for (int mi = 0; mi < 4; mi++)
#pragma unroll
                for (int ni = 0; ni < 2; ni++)
                    mma_f16(acc[mi][ni], a_h[mi], b_h[ni]);
        }
        __syncthreads();
    }

    if (outT) {
        __half* smT = (__half*)sm;
#pragma unroll
        for (int mi = 0; mi < 4; mi++) {
            int r = wm + mi * 16 + g;
            float nv0 = npm[bm + r] * scale, nv1 = npm[bm + r + 8] * scale;
#pragma unroll
            for (int ni = 0; ni < 2; ni++) {
                int c = wn + ni * 8 + 2 * tg;
                float b0 = bias[bn + c], b1 = bias[bn + c + 1];
                smT[c * 136 + r]           = __float2half((acc[mi][ni][0] + b0) * nv0);
                smT[(c + 1) * 136 + r]     = __float2half((acc[mi][ni][1] + b1) * nv0);
                smT[c * 136 + r + 8]       = __float2half((acc[mi][ni][2] + b0) * nv1);
                smT[(c + 1) * 136 + r + 8] = __float2half((acc[mi][ni][3] + b1) * nv1);
            }
        }
        __syncthreads();
        const int b = bm >> 10, token0 = bm & 1023;
#pragma unroll
        for (int p = 0; p < 4; p++) {
            int cr = (tid >> 4) + p * 32;
            int unit = tid & 15;
            int C = bn + cr;
            int h = C >> 6, d = C & 63;
            size_t dst = ((size_t)(b * 16 + h) * 64 + d) * 1024 + token0 + unit * 8;
            *(uint4*)&outT[dst] = *(const uint4*)&smT[cr * 136 + unit * 8];
        }
    } else if (outH) {
#pragma unroll
        for (int mi = 0; mi < 4; mi++) {
            int r0 = bm + wm + mi * 16 + g, r1 = r0 + 8;
            float nv0 = npm[r0] * scale, nv1 = npm[r1] * scale;
#pragma unroll
            for (int ni = 0; ni < 2; ni++) {
                int c0 = bn + wn + ni * 8 + 2 * tg;
                float b0 = bias[c0], b1 = bias[c0 + 1];
                *(__half2*)&outH[(size_t)r0 * DD + c0] =
                    __floats2half2_rn((acc[mi][ni][0] + b0) * nv0, (acc[mi][ni][1] + b1) * nv0);
                *(__half2*)&outH[(size_t)r1 * DD + c0] =
                    __floats2half2_rn((acc[mi][ni][2] + b0) * nv1, (acc[mi][ni][3] + b1) * nv1);
            }
        }
    } else {
#pragma unroll
        for (int mi = 0; mi < 4; mi++) {
            int r0 = bm + wm + mi * 16 + g, r1 = r0 + 8;
            float nv0 = npm[r0] * scale, nv1 = npm[r1] * scale;
#pragma unroll
            for (int ni = 0; ni < 2; ni++) {
                int c0 = bn + wn + ni * 8 + 2 * tg;
                float b0 = bias[c0], b1 = bias[c0 + 1];
                *(float2*)&outF[(size_t)r0 * DD + c0] =
                    make_float2((acc[mi][ni][0] + b0) * nv0, (acc[mi][ni][1] + b1) * nv0);
                *(float2*)&outF[(size_t)r1 * DD + c0] =
                    make_float2((acc[mi][ni][2] + b0) * nv1, (acc[mi][ni][3] + b1) * nv1);
            }
        }
    }
}

// ===========================================================================
// Fused attention: block = (b,h) x 32 q-rows, 512 threads
// S = QK^T fp16 (K quad-buffered, ldmatrix) -> mask+softmax (P fp16 smem)
// -> PV fp16 mma (V^T quad-buffered, ldmatrix)
// smem map: S f32 [0,131584) | Q @131584 (4608) | K 4x18432 @136192 = 209920
// overlays:  VT 4x17408 @0 (PV) | P 32x2096 @131584 (after S-phase)
// ===========================================================================
#define SSTR 1028
#define QOFF 131584
#define KOFF 136192
#define KBUF 18432
#define ATT_SMEM 209920
#define POFF QOFF
#define PSTRB 2096
#define VTSTRB 272
#define VTBUF 17408

__global__ __launch_bounds__(512) void attn_kernel(
    const __half* __restrict__ qh, const __half* __restrict__ kh,
    const __half* __restrict__ vhT, const int* __restrict__ mask,
    float* __restrict__ attn, __half* __restrict__ ctx)
{
    extern __shared__ char sm[];
    const uint32_t smb = smem_u32(sm);
    float* S = (float*)sm;

    const int tid = threadIdx.x, wid = tid >> 5, lane = tid & 31;
    const int g = lane >> 2, tg = lane & 3;
    const int lrow = lane & 15, lkh = (lane >> 4) * 16;
    const int bh = blockIdx.x;
    const int b = bh >> 4, h = bh & 15;
    const int q0 = blockIdx.y * 32;
    const int wq = wid & 1;
    const int wk = wid >> 1;

    const __half* qp_g = qh + ((size_t)b * LL + q0) * DD + h * DK;
    const __half* kp_g = kh + (size_t)b * LL * DD + h * DK;
    const __half* vTp = vhT + (size_t)bh * DK * LL;
    float* attnBase = attn + ((size_t)bh * LL + q0) * LL;

    // Q load + K0 (group 1), K1 (group 2)
    if (tid < 256) {
        int row = tid >> 3, c8 = tid & 7;
        cp16(smb + QOFF + row * 144 + c8 * 16, qp_g + (size_t)row * DD + c8 * 8);
    }
#pragma unroll
    for (int j = 0; j < 2; j++) {
        int idx = tid + 512 * j;
        int row = idx >> 3, c8 = idx & 7;
        cp16(smb + KOFF + row * 144 + c8 * 16, kp_g + (size_t)row * DD + c8 * 8);
    }
    CP_COMMIT;
#pragma unroll
    for (int j = 0; j < 2; j++) {
        int idx = tid + 512 * j;
        int row = idx >> 3, c8 = idx & 7;
        cp16(smb + KOFF + KBUF + row * 144 + c8 * 16,
             kp_g + (size_t)(128 + row) * DD + c8 * 8);
    }
    CP_COMMIT;

    // ---- S = Q K^T over 8 chunks, quad-buffered K ----
    for (int kc = 0; kc < 8; kc++) {
        if (kc < 6) {
#pragma unroll
            for (int j = 0; j < 2; j++) {
                int idx = tid + 512 * j;
                int row = idx >> 3, c8 = idx & 7;
                cp16(smb + KOFF + ((kc + 2) & 3) * KBUF + row * 144 + c8 * 16,
                     kp_g + (size_t)((kc + 2) * 128 + row) * DD + c8 * 8);
            }
            CP_COMMIT;
            CP_WAIT2;
        } else if (kc == 6) {
            CP_WAIT1;
        } else {
            CP_WAIT0;
        }
        __syncthreads();

        const uint32_t kb = smb + KOFF + (kc & 3) * KBUF;
        float sacc[2][4];
#pragma unroll
        for (int ni = 0; ni < 2; ni++)
#pragma unroll
            for (int r = 0; r < 4; r++) sacc[ni][r] = 0.f;

#pragma unroll
        for (int ks = 0; ks < 4; ks++) {
            uint32_t a_h[4], b4[4], b_h[2][2];
            ldsm4(a_h[0], a_h[1], a_h[2], a_h[3],
                  smb + QOFF + (wq * 16 + lrow) * 144 + ks * 32 + lkh);
            ldsm4(b4[0], b4[1], b4[2], b4[3],
                  kb + (wk * 16 + lrow) * 144 + ks * 32 + lkh);
            b_h[0][0] = b4[0]; b_h[0][1] = b4[2];
            b_h[1][0] = b4[1]; b_h[1][1] = b4[3];
            mma_f16(sacc[0], a_h, b_h[0]);
            mma_f16(sacc[1], a_h, b_h[1]);
        }
#pragma unroll
        for (int ni = 0; ni < 2; ni++) {
            int c = kc * 128 + wk * 16 + ni * 8 + 2 * tg;
            *(float2*)&S[(wq * 16 + g) * SSTR + c]     = make_float2(sacc[ni][0], sacc[ni][1]);
            *(float2*)&S[(wq * 16 + g + 8) * SSTR + c] = make_float2(sacc[ni][2], sacc[ni][3]);
        }
    }
    __syncthreads();

    // ---- mask + softmax; write attn (gmem) and P fp16 (smem @POFF) ----
#pragma unroll
    for (int rr = 0; rr < 2; rr++) {
        int r = wid * 2 + rr;
        float* Sr = S + r * SSTR;
        const int* mr = mask + ((size_t)b * LL + q0 + r) * LL;
        float m = -1e30f;
        for (int c = lane; c < 1024; c += 32) {
            float s = Sr[c];
            if (mr[c]) s = -1e30f;
            Sr[c] = s;
            m = fmaxf(m, s);
        }
#pragma unroll
        for (int o = 16; o; o >>= 1) m = fmaxf(m, __shfl_xor_sync(0xffffffffu, m, o));
        float sum = 0.f;
        for (int c = lane; c < 1024; c += 32) {
            float s = Sr[c];
            float e = (s <= -9e29f) ? 0.f : __expf(s - m);
            Sr[c] = e;
            sum += e;
        }
#pragma unroll
        for (int o = 16; o; o >>= 1) sum += __shfl_xor_sync(0xffffffffu, sum, o);
        float inv = 1.f / sum;
        float* dst = attnBase + (size_t)r * LL;
        __half* Pr = (__half*)(sm + POFF + r * PSTRB);
        for (int c = lane; c < 1024; c += 32) {
            float p = Sr[c] * inv;
            dst[c] = p;
            Pr[c] = __float2half(p);
        }
    }
    __syncthreads();   // P complete; S region dead -> VT buffers

    // prefetch V^T chunks 0,1 (groups 1,2)
#pragma unroll
    for (int j = 0; j < 2; j++) {
        int idx = tid + 512 * j;
        int d = idx >> 4, tk = idx & 15;
        cp16(smb + d * VTSTRB + tk * 16, vTp + (size_t)d * LL + tk * 8);
    }
    CP_COMMIT;
#pragma unroll
    for (int j = 0; j < 2; j++) {
        int idx = tid + 512 * j;
        int d = idx >> 4, tk = idx & 15;
        cp16(smb + VTBUF + d * VTSTRB + tk * 16, vTp + (size_t)d * LL + 128 + tk * 8);
    }
    CP_COMMIT;

    // ---- PV: fp16 mma, warp tile 16q x 8d, quad-buffered V^T ----
    float pacc[4] = {0.f, 0.f, 0.f, 0.f};
    for (int vc = 0; vc < 8; vc++) {
        if (vc < 6) {
#pragma unroll
            for (int j = 0; j < 2; j++) {
                int idx = tid + 512 * j;
                int d = idx >> 4, tk = idx & 15;
                cp16(smb + ((vc + 2) & 3) * VTBUF + d * VTSTRB + tk * 16,
                     vTp + (size_t)d * LL + (vc + 2) * 128 + tk * 8);
            }
            CP_COMMIT;
            CP_WAIT2;
        } else if (vc == 6) {
            CP_WAIT1;
        } else {
            CP_WAIT0;
        }
        __syncthreads();

        const uint32_t vtb = smb + (vc & 3) * VTBUF;
        const uint32_t pb = smb + POFF + (wq * 16) * PSTRB + vc * 256;
#pragma unroll
        for (int kk = 0; kk < 8; kk++) {
            uint32_t a[4], bfr[2];
            ldsm4(a[0], a[1], a[2], a[3], pb + lrow * PSTRB + kk * 32 + lkh);
            ldsm2(bfr[0], bfr[1],
                  vtb + (wk * 8 + (lane & 7)) * VTSTRB + kk * 32 + ((lane >> 3) & 1) * 16);
            mma_f16(pacc, a, bfr);
        }
    }

    {
        int c = h * DK + wk * 8 + 2 * tg;
        size_t r0 = (size_t)b * LL + q0 + wq * 16 + g;
        *(__half2*)&ctx[r0 * DD + c]       = __floats2half2_rn(pacc[0], pacc[1]);
        *(__half2*)&ctx[(r0 + 8) * DD + c] = __floats2half2_rn(pacc[2], pacc[3]);
    }
}

// ---------------------------------------------------------------------------
// LayerNorm(proj + residual) * g + b
// ---------------------------------------------------------------------------
__global__ __launch_bounds__(256) void ln_kernel(
    const float* __restrict__ proj, const float* __restrict__ resid,
    const float* __restrict__ gam, const float* __restrict__ bet,
    float* __restrict__ out)
{
    __shared__ float red[8];
    const int row = blockIdx.x;
    const int tid = threadIdx.x;
    const int c0 = tid * 4;
    const int lane = tid & 31, wid = tid >> 5;

    float4 pv = *(const float4*)(proj + (size_t)row * DD + c0);
    float4 rv = *(const float4*)(resid + (size_t)row * DD + c0);
    float x0 = pv.x + rv.x, x1 = pv.y + rv.y, x2 = pv.z + rv.z, x3 = pv.w + rv.w;

    float s = x0 + x1 + x2 + x3;
#pragma unroll
    for (int o = 16; o; o >>= 1) s += __shfl_xor_sync(0xffffffffu, s, o);
    if (lane == 0) red[wid] = s;
    __syncthreads();
    float tot = (lane < 8) ? red[lane] : 0.f;
#pragma unroll
    for (int o = 4; o; o >>= 1) tot += __shfl_xor_sync(0xffffffffu, tot, o);
    tot = __shfl_sync(0xffffffffu, tot, 0);
    float mean = tot * (1.f / 1024.f);

    float d0 = x0 - mean, d1 = x1 - mean, d2 = x2 - mean, d3 = x3 - mean;
    float sq = d0 * d0 + d1 * d1 + d2 * d2 + d3 * d3;
#pragma unroll
    for (int o = 16; o; o >>= 1) sq += __shfl_xor_sync(0xffffffffu, sq, o);
    __syncthreads();
    if (lane == 0) red[wid] = sq;
    __syncthreads();
    float tot2 = (lane < 8) ? red[lane] : 0.f;
#pragma unroll
    for (int o = 4; o; o >>= 1) tot2 += __shfl_xor_sync(0xffffffffu, tot2, o);
    tot2 = __shfl_sync(0xffffffffu, tot2, 0);
    float k = rsqrtf(tot2 * (1.f / 1024.f) + 1e-5f);

    float4 gv = *(const float4*)(gam + c0);
    float4 bv = *(const float4*)(bet + c0);
    float4 ov;
    ov.x = d0 * k * gv.x + bv.x;
    ov.y = d1 * k * gv.y + bv.y;
    ov.z = d2 * k * gv.z + bv.z;
    ov.w = d3 * k * gv.w + bv.w;
    *(float4*)&out[(size_t)row * DD + c0] = ov;
}

// ---------------------------------------------------------------------------
extern "C" void kernel_launch(void* const* d_in, const int* in_sizes, int n_in,
                              void* d_out, int out_size)
{
    const float* q    = (const float*)d_in[0];
    const float* k    = (const float*)d_in[1];
    const float* v    = (const float*)d_in[2];
    const int*   mask = (const int*)  d_in[3];
    const float* npm  = (const float*)d_in[4];
    const float* Wq   = (const float*)d_in[5];
    const float* bq   = (const float*)d_in[6];
    const float* Wk   = (const float*)d_in[7];
    const float* bk   = (const float*)d_in[8];
    const float* Wv   = (const float*)d_in[9];
    const float* bv   = (const float*)d_in[10];
    const float* Wf   = (const float*)d_in[11];
    const float* bf   = (const float*)d_in[12];
    const float* ln_g = (const float*)d_in[13];
    const float* ln_b = (const float*)d_in[14];

    float* out  = (float*)d_out;
    float* attn = out + (size_t)BB * LL * DD;

    __half *qh, *kh, *vhT, *ctx, *as, *ws;
    float *proj;
    cudaGetSymbolAddress((void**)&qh,  g_qh);
    cudaGetSymbolAddress((void**)&kh,  g_kh);
    cudaGetSymbolAddress((void**)&vhT, g_vhT);
    cudaGetSymbolAddress((void**)&ctx, g_ctx);
    cudaGetSymbolAddress((void**)&proj, g_proj);
    cudaGetSymbolAddress((void**)&as,  g_as);
    cudaGetSymbolAddress((void**)&ws,  g_ws);

    cudaFuncSetAttribute(gemm_f16_1t, cudaFuncAttributeMaxDynamicSharedMemorySize, GEMM1_SMEM);
    cudaFuncSetAttribute(attn_kernel, cudaFuncAttributeMaxDynamicSharedMemorySize, ATT_SMEM);

    const int nA4 = ROWS_TOT * DD / 4;
    const int nW4 = DD * DD / 4;
    dim3 gG(DD / 128, ROWS_TOT / 128);   // (8, 64)

    // Q projection (scale 1/8 folded) -> fp16
    conv_f16<<<(nA4 + 255) / 256, 256>>>(q, as, nA4);
    conv_f16<<<(nW4 + 255) / 256, 256>>>(Wq, ws, nW4);
    gemm_f16_1t<<<gG, 512, GEMM1_SMEM>>>(as, ws, bq, npm, 0.125f, nullptr, qh, nullptr);
    // K projection -> fp16
    conv_f16<<<(nA4 + 255) / 256, 256>>>(k, as, nA4);
    conv_f16<<<(nW4 + 255) / 256, 256>>>(Wk, ws, nW4);
    gemm_f16_1t<<<gG, 512, GEMM1_SMEM>>>(as, ws, bk, npm, 1.0f, nullptr, kh, nullptr);
    // V projection -> transposed fp16 vhT
    conv_f16<<<(nA4 + 255) / 256, 256>>>(v, as, nA4);
    conv_f16<<<(nW4 + 255) / 256, 256>>>(Wv, ws, nW4);
    gemm_f16_1t<<<gG, 512, GEMM1_SMEM>>>(as, ws, bv, npm, 1.0f, nullptr, nullptr, vhT);

    // Fused attention (ctx out as fp16)
    attn_kernel<<<dim3(BB * HH, LL / 32), 512, ATT_SMEM>>>(
        qh, kh, vhT, mask, attn, ctx);

    // Output projection (ctx fp16 direct) -> fp32, then LN
    conv_f16<<<(nW4 + 255) / 256, 256>>>(Wf, ws, nW4);
    gemm_f16_1t<<<gG, 512, GEMM1_SMEM>>>(ctx, ws, bf, npm, 1.0f, proj, nullptr, nullptr);

    ln_kernel<<<ROWS_TOT, 256>>>(proj, q, ln_g, ln_b, out);
}